// round 2
// baseline (speedup 1.0000x reference)
#include <cuda_runtime.h>
#include <math.h>

#define BATCH 8192
#define DIM   512
#define NREG  4
#define NS    6
#define HIDN  128
#define NHEAD 4
#define HD    128

// db8 lowpass (pywt 'periodization')
__constant__ float c_lo[16] = {
    -0.00011747678400228192f, 0.0006754494059985568f, -0.0003917403729959771f,
    -0.00487035299301066f,    0.008746094047015655f,  0.013981027917015516f,
    -0.04408825393106472f,    -0.01736930100202211f,  0.128747426620186f,
    0.00047248457399797254f,  -0.2840155429624281f,   -0.015829105256023893f,
    0.5853546836548691f,      0.6756307362980128f,    0.3128715909144659f,
    0.05441584224308161f
};

__constant__ int c_off[NS] = {0, 16, 32, 64, 128, 256};
__constant__ int c_len[NS] = {16, 16, 32, 64, 128, 256};

// ---- scratch (static device globals; no runtime allocation) ----
__device__ float g_coeffs[BATCH * DIM];          // packed wavelet coeffs (16 MB)
__device__ float g_H[BATCH * DIM];               // gating hidden, all 4 regimes
__device__ float g_wts[BATCH * NS];              // softmax gate weights
__device__ float g_W1cat[DIM * DIM];             // W1 repacked (d, r*128+j)
__device__ float g_biasH[DIM];                   // b1 + onehot rows
__device__ float g_Apack[DIM * DIM];             // Wp packed into coeff space
__device__ float g_Wf[3 * DIM * DIM];            // fused Wp@{Wq,Wk,Wv}
__device__ float g_biasf[3 * NS * DIM];          // fused biases bp@W + b
__device__ float g_QKV[3ll * BATCH * NS * DIM];  // q,k,v (300 MB)
__device__ float g_pre[BATCH * DIM];             // gate-weighted attn output
__device__ float g_agg[BATCH * DIM];             // pre @ Wo + bo

// =====================================================================
// 1) DWT: 5 levels db8 periodization, packed output
//    layout: [a5(16) | d5(16) | d4(32) | d3(64) | d2(128) | d1(256)]
// =====================================================================
__global__ void dwt_kernel(const float* __restrict__ x, float* __restrict__ coeffs)
{
    int b = blockIdx.x;
    __shared__ float buf0[DIM], buf1[DIM];
    float* cur = buf0;
    float* nxt = buf1;
    for (int d = threadIdx.x; d < DIM; d += blockDim.x)
        cur[d] = x[(size_t)b * DIM + d];
    __syncthreads();

    int n = DIM;
    #pragma unroll
    for (int lev = 0; lev < 5; lev++) {
        int nh = n >> 1;
        for (int k = threadIdx.x; k < nh; k += blockDim.x) {
            float sa = 0.f, sd = 0.f;
            #pragma unroll
            for (int j = 0; j < 16; j++) {
                int m = 2 * k + 1 - j;
                if (m < 0) m += n;
                float av = cur[m];
                float hj = c_lo[15 - j] * ((j & 1) ? 1.f : -1.f);
                sa += c_lo[j] * av;
                sd += hj * av;
            }
            nxt[k] = sa;
            coeffs[(size_t)b * DIM + nh + k] = sd;  // detail at offset = len
        }
        __syncthreads();
        float* t = cur; cur = nxt; nxt = t;
        n = nh;
    }
    for (int k = threadIdx.x; k < 16; k += blockDim.x)
        coeffs[(size_t)b * DIM + k] = cur[k];
}

// =====================================================================
// 2) weight repacking: W1cat, biasH, Apack
// =====================================================================
__global__ void prep_pack(const float* __restrict__ W1, const float* __restrict__ b1,
                          const float* __restrict__ Wp,
                          float* __restrict__ W1cat, float* __restrict__ biasH,
                          float* __restrict__ Apack)
{
    int row = blockIdx.x;       // 0..511
    int c   = threadIdx.x;      // 0..511
    int r = c >> 7, j = c & 127;
    // W1 layout (R, D+R, HID): (r,d,j) -> r*516*128 + d*128 + j
    W1cat[row * DIM + c] = W1[r * (516 * 128) + row * 128 + j];

    int s, k;
    if      (row < 16)  { s = 0; k = row;       }
    else if (row < 32)  { s = 1; k = row - 16;  }
    else if (row < 64)  { s = 2; k = row - 32;  }
    else if (row < 128) { s = 3; k = row - 64;  }
    else if (row < 256) { s = 4; k = row - 128; }
    else                { s = 5; k = row - 256; }
    Apack[row * DIM + c] = Wp[s * (DIM * DIM) + k * DIM + c];

    if (row == 0)
        biasH[c] = b1[r * 128 + j] + W1[r * (516 * 128) + (512 + r) * 128 + j];
}

// biasf[t][s][d] = bp[s]@W_t[:,d] + b_t[d]
__global__ void prep_biasf(const float* __restrict__ bp,
                           const float* __restrict__ Wq, const float* __restrict__ Wk,
                           const float* __restrict__ Wv,
                           const float* __restrict__ bq, const float* __restrict__ bk,
                           const float* __restrict__ bv, float* __restrict__ biasf)
{
    int z = blockIdx.x;           // 0..17
    int t = z / NS, s = z % NS;
    int d = threadIdx.x;          // 512
    const float* W    = (t == 0) ? Wq : (t == 1) ? Wk : Wv;
    const float* bvec = (t == 0) ? bq : (t == 1) ? bk : bv;
    __shared__ float bps[DIM];
    bps[d] = bp[s * DIM + d];
    __syncthreads();
    float acc = 0.f;
    for (int e = 0; e < DIM; e++)
        acc += bps[e] * W[e * DIM + d];
    biasf[(t * NS + s) * DIM + d] = acc + bvec[d];
}

// =====================================================================
// 3) fp32 GEMM tile body: C[M,N] = A[M,K]@B[K,N] (+bias, opt relu)
//    64x64 tile, BK=16, 256 threads, 4x4 per thread.
//    Requires K%16==0, float4-aligned pointers.
// =====================================================================
__device__ __forceinline__ void gemm_tile(
    const float* __restrict__ A, int lda,
    const float* __restrict__ B, int ldb,
    float* __restrict__ C, int ldc, int K,
    const float* __restrict__ bias, int doRelu,
    int bm, int bn)
{
    __shared__ float As[16][64];
    __shared__ float Bs[16][64];
    int t  = threadIdx.x;
    int tx = t & 15, ty = t >> 4;
    int aRow = t >> 2,  aCol = (t & 3) * 4;
    int bRow = t >> 4,  bCol = (t & 15) * 4;

    float acc[4][4] = {};
    for (int k0 = 0; k0 < K; k0 += 16) {
        float4 av = *(const float4*)&A[(size_t)(bm + aRow) * lda + k0 + aCol];
        As[aCol + 0][aRow] = av.x;
        As[aCol + 1][aRow] = av.y;
        As[aCol + 2][aRow] = av.z;
        As[aCol + 3][aRow] = av.w;
        float4 bv = *(const float4*)&B[(size_t)(k0 + bRow) * ldb + bn + bCol];
        *(float4*)&Bs[bRow][bCol] = bv;
        __syncthreads();
        #pragma unroll
        for (int kk = 0; kk < 16; kk++) {
            float4 a4 = *(const float4*)&As[kk][ty * 4];
            float4 b4 = *(const float4*)&Bs[kk][tx * 4];
            float ar[4] = {a4.x, a4.y, a4.z, a4.w};
            float br[4] = {b4.x, b4.y, b4.z, b4.w};
            #pragma unroll
            for (int i = 0; i < 4; i++)
                #pragma unroll
                for (int j = 0; j < 4; j++)
                    acc[i][j] += ar[i] * br[j];
        }
        __syncthreads();
    }
    int n0 = bn + tx * 4;
    #pragma unroll
    for (int i = 0; i < 4; i++) {
        float4 r;
        r.x = acc[i][0]; r.y = acc[i][1]; r.z = acc[i][2]; r.w = acc[i][3];
        if (bias) { r.x += bias[n0]; r.y += bias[n0+1]; r.z += bias[n0+2]; r.w += bias[n0+3]; }
        if (doRelu) {
            r.x = fmaxf(r.x, 0.f); r.y = fmaxf(r.y, 0.f);
            r.z = fmaxf(r.z, 0.f); r.w = fmaxf(r.w, 0.f);
        }
        *(float4*)&C[(size_t)(bm + ty * 4 + i) * ldc + n0] = r;
    }
}

__global__ __launch_bounds__(256) void gemm64(
    const float* __restrict__ A, int lda,
    const float* __restrict__ B, int ldb,
    float* __restrict__ C, int ldc, int K,
    const float* __restrict__ bias, int doRelu)
{
    gemm_tile(A, lda, B, ldb, C, ldc, K, bias, doRelu,
              blockIdx.y * 64, blockIdx.x * 64);
}

// all 18 (tensor,scale) QKV GEMMs in one launch: blockIdx.z -> (t,s)
__global__ __launch_bounds__(256) void gemm_qkv(
    const float* __restrict__ coeffs, const float* __restrict__ Wf,
    const float* __restrict__ biasf, float* __restrict__ QKV)
{
    int z = blockIdx.z;
    int t = z / NS, s = z % NS;
    int off = c_off[s], len = c_len[s];
    const size_t STRIDE = (size_t)BATCH * NS * DIM;
    gemm_tile(coeffs + off, DIM,
              Wf + (size_t)t * DIM * DIM + (size_t)off * DIM, DIM,
              QKV + (size_t)t * STRIDE + s * DIM, NS * DIM,
              len,
              biasf + (t * NS + s) * DIM, 0,
              blockIdx.y * 64, blockIdx.x * 64);
}

// =====================================================================
// 4) gating: pick regime r, logits = h@W2[r]+b2[r], softmax -> w (B,6)
//    one warp per row
// =====================================================================
__global__ void gating_kernel(const float* __restrict__ H, const int* __restrict__ labels,
                              const float* __restrict__ W2, const float* __restrict__ b2,
                              float* __restrict__ w)
{
    int warp = threadIdx.x >> 5, lane = threadIdx.x & 31;
    int b = blockIdx.x * 8 + warp;
    if (b >= BATCH) return;
    int r = labels[b];
    const float* h  = H + (size_t)b * DIM + r * 128;
    const float* w2 = W2 + r * (HIDN * NS);
    float acc[NS] = {0, 0, 0, 0, 0, 0};
    for (int j = lane; j < HIDN; j += 32) {
        float hv = h[j];
        #pragma unroll
        for (int s = 0; s < NS; s++) acc[s] += hv * w2[j * NS + s];
    }
    #pragma unroll
    for (int s = 0; s < NS; s++)
        #pragma unroll
        for (int o = 16; o > 0; o >>= 1)
            acc[s] += __shfl_down_sync(0xffffffffu, acc[s], o);
    if (lane == 0) {
        float m = -1e30f;
        #pragma unroll
        for (int s = 0; s < NS; s++) { acc[s] += b2[r * NS + s]; m = fmaxf(m, acc[s]); }
        float sum = 0.f;
        #pragma unroll
        for (int s = 0; s < NS; s++) { acc[s] = expf(acc[s] - m); sum += acc[s]; }
        float inv = 1.f / sum;
        #pragma unroll
        for (int s = 0; s < NS; s++) w[(size_t)b * NS + s] = acc[s] * inv;
    }
}

// =====================================================================
// 5) attention (S=6, 4 heads) + gate-weighted sum -> pre (B,512)
//    one block (4 warps = 1 warp/head) per batch row
// =====================================================================
__global__ __launch_bounds__(128) void attn_kernel(
    const float* __restrict__ Q, const float* __restrict__ K, const float* __restrict__ V,
    const float* __restrict__ w, float* __restrict__ pre)
{
    int b = blockIdx.x;
    int h = threadIdx.x >> 5, lane = threadIdx.x & 31;
    __shared__ float sq[NHEAD][NS][HD];
    __shared__ float sk[NHEAD][NS][HD];
    __shared__ float sv[NHEAD][NS][HD];
    __shared__ float att[NHEAD][NS][NS];
    __shared__ float ww[NHEAD][NS];

    size_t base = (size_t)b * (NS * DIM) + h * HD;
    #pragma unroll
    for (int s = 0; s < NS; s++)
        for (int d = lane; d < HD; d += 32) {
            sq[h][s][d] = Q[base + s * DIM + d];
            sk[h][s][d] = K[base + s * DIM + d];
            sv[h][s][d] = V[base + s * DIM + d];
        }
    __syncwarp();

    const float scale = 0.08838834764831845f; // 1/sqrt(128)
    for (int p = lane; p < NS * NS; p += 32) {
        int i = p / NS, j = p % NS;
        float s0 = 0.f;
        #pragma unroll 8
        for (int d = 0; d < HD; d++) s0 += sq[h][i][d] * sk[h][j][d];
        att[h][i][j] = s0 * scale;
    }
    __syncwarp();
    if (lane < NS) {
        int i = lane;
        float m = -1e30f;
        #pragma unroll
        for (int j = 0; j < NS; j++) m = fmaxf(m, att[h][i][j]);
        float e[NS], sum = 0.f;
        #pragma unroll
        for (int j = 0; j < NS; j++) { e[j] = expf(att[h][i][j] - m); sum += e[j]; }
        float inv = 1.f / sum;
        #pragma unroll
        for (int j = 0; j < NS; j++) att[h][i][j] = e[j] * inv;
    }
    __syncwarp();
    if (lane < NS) {
        int j = lane;
        float t = 0.f;
        #pragma unroll
        for (int i = 0; i < NS; i++) t += w[(size_t)b * NS + i] * att[h][i][j];
        ww[h][j] = t;
    }
    __syncwarp();
    for (int d = lane; d < HD; d += 32) {
        float o = 0.f;
        #pragma unroll
        for (int j = 0; j < NS; j++) o += ww[h][j] * sv[h][j][d];
        pre[(size_t)b * DIM + h * HD + d] = o;
    }
}

// =====================================================================
// 6) residual + layernorm
// =====================================================================
__global__ __launch_bounds__(256) void ln_kernel(
    const float* __restrict__ x, const float* __restrict__ agg,
    const float* __restrict__ g, const float* __restrict__ be,
    float* __restrict__ out)
{
    int b = blockIdx.x, tid = threadIdx.x;
    __shared__ float rs[8], rq[8];
    size_t base = (size_t)b * DIM;
    float y0 = x[base + tid]       + agg[base + tid];
    float y1 = x[base + tid + 256] + agg[base + tid + 256];
    float s = y0 + y1, q = y0 * y0 + y1 * y1;
    #pragma unroll
    for (int o = 16; o > 0; o >>= 1) {
        s += __shfl_down_sync(0xffffffffu, s, o);
        q += __shfl_down_sync(0xffffffffu, q, o);
    }
    int warp = tid >> 5, lane = tid & 31;
    if (lane == 0) { rs[warp] = s; rq[warp] = q; }
    __syncthreads();
    if (tid == 0) {
        float ts = 0.f, tq = 0.f;
        #pragma unroll
        for (int i = 0; i < 8; i++) { ts += rs[i]; tq += rq[i]; }
        rs[0] = ts; rq[0] = tq;
    }
    __syncthreads();
    float mu  = rs[0] * (1.f / DIM);
    float var = rq[0] * (1.f / DIM) - mu * mu;
    float rstd = rsqrtf(var + 1e-5f);
    out[base + tid]       = (y0 - mu) * rstd * g[tid]       + be[tid];
    out[base + tid + 256] = (y1 - mu) * rstd * g[tid + 256] + be[tid + 256];
}

// =====================================================================
// host
// =====================================================================
extern "C" void kernel_launch(void* const* d_in, const int* in_sizes, int n_in,
                              void* d_out, int out_size)
{
    // detect input ordering: insertion (x first) vs alphabetical (W1 first)
    bool ins = (in_sizes[0] == BATCH * DIM);
    auto P = [&](int i_ins, int i_alpha) -> const float* {
        return (const float*)d_in[ins ? i_ins : i_alpha];
    };
    const float* x   = P(0, 17);
    const float* W1  = P(1, 0);
    const float* b1  = P(2, 7);
    const float* W2  = P(3, 1);
    const float* b2  = P(4, 8);
    const float* Wp  = P(5, 4);
    const float* bp  = P(6, 11);
    const float* Wq  = P(7, 5);  const float* bq = P(8, 12);
    const float* Wk  = P(9, 2);  const float* bk = P(10, 9);
    const float* Wv  = P(11, 6); const float* bv = P(12, 13);
    const float* Wo  = P(13, 3); const float* bo = P(14, 10);
    const float* lng = P(15, 15);
    const float* lnb = P(16, 14);
    const int* labels = (const int*)d_in[ins ? 17 : 16];
    float* out = (float*)d_out;

    float *coeffs, *H, *wts, *W1cat, *biasH, *Apack, *Wf, *biasf, *QKV, *pre, *agg;
    cudaGetSymbolAddress((void**)&coeffs, g_coeffs);
    cudaGetSymbolAddress((void**)&H,      g_H);
    cudaGetSymbolAddress((void**)&wts,    g_wts);
    cudaGetSymbolAddress((void**)&W1cat,  g_W1cat);
    cudaGetSymbolAddress((void**)&biasH,  g_biasH);
    cudaGetSymbolAddress((void**)&Apack,  g_Apack);
    cudaGetSymbolAddress((void**)&Wf,     g_Wf);
    cudaGetSymbolAddress((void**)&biasf,  g_biasf);
    cudaGetSymbolAddress((void**)&QKV,    g_QKV);
    cudaGetSymbolAddress((void**)&pre,    g_pre);
    cudaGetSymbolAddress((void**)&agg,    g_agg);

    const size_t QKV_STRIDE = (size_t)BATCH * NS * DIM;

    // 1. wavelet transform
    dwt_kernel<<<BATCH, 256>>>(x, coeffs);

    // 2. weight repack + fused-weight GEMMs + fused biases
    prep_pack<<<512, 512>>>(W1, b1, Wp, W1cat, biasH, Apack);
    gemm64<<<dim3(8, 8), 256>>>(Apack, DIM, Wq, DIM, Wf + 0 * DIM * DIM, DIM, DIM, nullptr, 0);
    gemm64<<<dim3(8, 8), 256>>>(Apack, DIM, Wk, DIM, Wf + 1 * DIM * DIM, DIM, DIM, nullptr, 0);
    gemm64<<<dim3(8, 8), 256>>>(Apack, DIM, Wv, DIM, Wf + 2 * DIM * DIM, DIM, DIM, nullptr, 0);
    prep_biasf<<<18, 512>>>(bp, Wq, Wk, Wv, bq, bk, bv, biasf);

    // 3. gating: H = relu(x@W1cat + biasH), then per-row regime select + softmax
    gemm64<<<dim3(8, 128), 256>>>(x, DIM, W1cat, DIM, H, DIM, DIM, biasH, 1);
    gating_kernel<<<BATCH / 8, 256>>>(H, labels, W2, b2, wts);

    // 4. packed QKV: all 18 (tensor, scale) GEMMs in one launch
    gemm_qkv<<<dim3(8, 128, 18), 256>>>(coeffs, Wf, biasf, QKV);

    // 5. attention + gate-weighted combine (Wo folded out of the S loop)
    attn_kernel<<<BATCH, 128>>>(QKV, QKV + QKV_STRIDE, QKV + 2 * QKV_STRIDE, wts, pre);

    // 6. output projection, residual, layernorm
    gemm64<<<dim3(8, 128), 256>>>(pre, DIM, Wo, DIM, agg, DIM, DIM, bo, 0);
    ln_kernel<<<BATCH, 256>>>(x, agg, lng, lnb, out);
}

// round 3
// speedup vs baseline: 1.6845x; 1.6845x over previous
#include <cuda_runtime.h>
#include <math.h>

#define BATCH 8192
#define DIM   512
#define NREG  4
#define NS    6
#define HIDN  128
#define NHEAD 4
#define HD    128

// db8 lowpass (pywt 'periodization')
__constant__ float c_lo[16] = {
    -0.00011747678400228192f, 0.0006754494059985568f, -0.0003917403729959771f,
    -0.00487035299301066f,    0.008746094047015655f,  0.013981027917015516f,
    -0.04408825393106472f,    -0.01736930100202211f,  0.128747426620186f,
    0.00047248457399797254f,  -0.2840155429624281f,   -0.015829105256023893f,
    0.5853546836548691f,      0.6756307362980128f,    0.3128715909144659f,
    0.05441584224308161f
};

__constant__ int c_off[NS] = {0, 16, 32, 64, 128, 256};
__constant__ int c_len[NS] = {16, 16, 32, 64, 128, 256};

// ---- scratch (static device globals; no runtime allocation) ----
__device__ float g_coeffs[BATCH * DIM];
__device__ float g_H[BATCH * DIM];
__device__ float g_wts[BATCH * NS];
__device__ float g_W1cat[DIM * DIM];
__device__ float g_biasH[DIM];
__device__ float g_Apack[DIM * DIM];
__device__ float g_Wf[3 * DIM * DIM];
__device__ float g_biasf[3 * NS * DIM];
__device__ float g_QKV[3ll * BATCH * NS * DIM];
__device__ float g_pre[BATCH * DIM];
__device__ float g_agg[BATCH * DIM];

// =====================================================================
// 1) DWT: 5 levels db8 periodization, packed output
// =====================================================================
__global__ void dwt_kernel(const float* __restrict__ x, float* __restrict__ coeffs)
{
    int b = blockIdx.x;
    __shared__ float buf0[DIM], buf1[DIM];
    float* cur = buf0;
    float* nxt = buf1;
    for (int d = threadIdx.x; d < DIM; d += blockDim.x)
        cur[d] = x[(size_t)b * DIM + d];
    __syncthreads();

    int n = DIM;
    #pragma unroll
    for (int lev = 0; lev < 5; lev++) {
        int nh = n >> 1;
        for (int k = threadIdx.x; k < nh; k += blockDim.x) {
            float sa = 0.f, sd = 0.f;
            #pragma unroll
            for (int j = 0; j < 16; j++) {
                int m = 2 * k + 1 - j;
                if (m < 0) m += n;
                float av = cur[m];
                float hj = c_lo[15 - j] * ((j & 1) ? 1.f : -1.f);
                sa += c_lo[j] * av;
                sd += hj * av;
            }
            nxt[k] = sa;
            coeffs[(size_t)b * DIM + nh + k] = sd;
        }
        __syncthreads();
        float* t = cur; cur = nxt; nxt = t;
        n = nh;
    }
    for (int k = threadIdx.x; k < 16; k += blockDim.x)
        coeffs[(size_t)b * DIM + k] = cur[k];
}

// =====================================================================
// 2) weight repacking
// =====================================================================
__global__ void prep_pack(const float* __restrict__ W1, const float* __restrict__ b1,
                          const float* __restrict__ Wp,
                          float* __restrict__ W1cat, float* __restrict__ biasH,
                          float* __restrict__ Apack)
{
    int row = blockIdx.x;
    int c   = threadIdx.x;
    int r = c >> 7, j = c & 127;
    W1cat[row * DIM + c] = W1[r * (516 * 128) + row * 128 + j];

    int s, k;
    if      (row < 16)  { s = 0; k = row;       }
    else if (row < 32)  { s = 1; k = row - 16;  }
    else if (row < 64)  { s = 2; k = row - 32;  }
    else if (row < 128) { s = 3; k = row - 64;  }
    else if (row < 256) { s = 4; k = row - 128; }
    else                { s = 5; k = row - 256; }
    Apack[row * DIM + c] = Wp[s * (DIM * DIM) + k * DIM + c];

    if (row == 0)
        biasH[c] = b1[r * 128 + j] + W1[r * (516 * 128) + (512 + r) * 128 + j];
}

__global__ void prep_biasf(const float* __restrict__ bp,
                           const float* __restrict__ Wq, const float* __restrict__ Wk,
                           const float* __restrict__ Wv,
                           const float* __restrict__ bq, const float* __restrict__ bk,
                           const float* __restrict__ bv, float* __restrict__ biasf)
{
    int z = blockIdx.x;
    int t = z / NS, s = z % NS;
    int d = threadIdx.x;
    const float* W    = (t == 0) ? Wq : (t == 1) ? Wk : Wv;
    const float* bvec = (t == 0) ? bq : (t == 1) ? bk : bv;
    __shared__ float bps[DIM];
    bps[d] = bp[s * DIM + d];
    __syncthreads();
    float acc = 0.f;
    for (int e = 0; e < DIM; e++)
        acc += bps[e] * W[e * DIM + d];
    biasf[(t * NS + s) * DIM + d] = acc + bvec[d];
}

// =====================================================================
// 3) tf32 tensor-core GEMM: C[M,N] = A[M,K]@B[K,N] (+bias, opt relu)
//    128x128 block tile, BK=16, 8 warps (64x32 warp tile), mma.m16n8k8
//    Requires M%128==0, N%128==0, K%16==0, float4-aligned pointers.
// =====================================================================
__device__ __forceinline__ unsigned f2tf(float x) {
    unsigned u;
    asm("cvt.rna.tf32.f32 %0, %1;" : "=r"(u) : "f"(x));
    return u;
}

__device__ __forceinline__ void gemm_tf32_tile(
    const float* __restrict__ A, int lda,
    const float* __restrict__ B, int ldb,
    float* __restrict__ C, int ldc, int K,
    const float* __restrict__ bias, int doRelu,
    int bm, int bn)
{
    __shared__ float As[128][20];   // [m][k], pad 20 -> conflict-free frag loads
    __shared__ float Bs[16][136];   // [k][n], pad 136 -> conflict-free frag loads
    int t = threadIdx.x;
    int warp = t >> 5, lane = t & 31;
    int wm = (warp >> 2) * 64;      // 2 warp rows
    int wn = (warp & 3) * 32;       // 4 warp cols
    int gid = lane >> 2, tig = lane & 3;

    float c[4][4][4];
    #pragma unroll
    for (int i = 0; i < 4; i++)
        #pragma unroll
        for (int j = 0; j < 4; j++)
            #pragma unroll
            for (int r = 0; r < 4; r++) c[i][j][r] = 0.f;

    for (int k0 = 0; k0 < K; k0 += 16) {
        // stage A tile (128x16): 512 float4, 2 per thread
        #pragma unroll
        for (int i = 0; i < 2; i++) {
            int f = t + i * 256;
            int row = f >> 2, c4 = (f & 3) << 2;
            float4 v = *(const float4*)&A[(size_t)(bm + row) * lda + k0 + c4];
            As[row][c4 + 0] = __uint_as_float(f2tf(v.x));
            As[row][c4 + 1] = __uint_as_float(f2tf(v.y));
            As[row][c4 + 2] = __uint_as_float(f2tf(v.z));
            As[row][c4 + 3] = __uint_as_float(f2tf(v.w));
        }
        // stage B tile (16x128): 512 float4, 2 per thread
        #pragma unroll
        for (int i = 0; i < 2; i++) {
            int f = t + i * 256;
            int row = f >> 5, c4 = (f & 31) << 2;
            float4 v = *(const float4*)&B[(size_t)(k0 + row) * ldb + bn + c4];
            Bs[row][c4 + 0] = __uint_as_float(f2tf(v.x));
            Bs[row][c4 + 1] = __uint_as_float(f2tf(v.y));
            Bs[row][c4 + 2] = __uint_as_float(f2tf(v.z));
            Bs[row][c4 + 3] = __uint_as_float(f2tf(v.w));
        }
        __syncthreads();

        #pragma unroll
        for (int kk = 0; kk < 16; kk += 8) {
            unsigned a[4][4], b[4][2];
            #pragma unroll
            for (int mi = 0; mi < 4; mi++) {
                const float* p = &As[wm + mi * 16 + gid][kk + tig];
                a[mi][0] = __float_as_uint(p[0]);
                a[mi][1] = __float_as_uint(p[8 * 20]);
                a[mi][2] = __float_as_uint(p[4]);
                a[mi][3] = __float_as_uint(p[8 * 20 + 4]);
            }
            #pragma unroll
            for (int ni = 0; ni < 4; ni++) {
                const float* p = &Bs[kk + tig][wn + ni * 8 + gid];
                b[ni][0] = __float_as_uint(p[0]);
                b[ni][1] = __float_as_uint(p[4 * 136]);
            }
            #pragma unroll
            for (int mi = 0; mi < 4; mi++)
                #pragma unroll
                for (int ni = 0; ni < 4; ni++)
                    asm volatile(
                        "mma.sync.aligned.m16n8k8.row.col.f32.tf32.tf32.f32 "
                        "{%0,%1,%2,%3}, {%4,%5,%6,%7}, {%8,%9}, {%0,%1,%2,%3};"
                        : "+f"(c[mi][ni][0]), "+f"(c[mi][ni][1]),
                          "+f"(c[mi][ni][2]), "+f"(c[mi][ni][3])
                        : "r"(a[mi][0]), "r"(a[mi][1]), "r"(a[mi][2]), "r"(a[mi][3]),
                          "r"(b[ni][0]), "r"(b[ni][1]));
        }
        __syncthreads();
    }

    // epilogue: c0=C[r][col], c1=C[r][col+1], c2=C[r+8][col], c3=C[r+8][col+1]
    #pragma unroll
    for (int mi = 0; mi < 4; mi++) {
        int r0 = bm + wm + mi * 16 + gid;
        #pragma unroll
        for (int ni = 0; ni < 4; ni++) {
            int col = bn + wn + ni * 8 + tig * 2;
            float b0 = 0.f, b1 = 0.f;
            if (bias) { b0 = bias[col]; b1 = bias[col + 1]; }
            float v0 = c[mi][ni][0] + b0, v1 = c[mi][ni][1] + b1;
            float v2 = c[mi][ni][2] + b0, v3 = c[mi][ni][3] + b1;
            if (doRelu) {
                v0 = fmaxf(v0, 0.f); v1 = fmaxf(v1, 0.f);
                v2 = fmaxf(v2, 0.f); v3 = fmaxf(v3, 0.f);
            }
            *(float2*)&C[(size_t)r0 * ldc + col]       = make_float2(v0, v1);
            *(float2*)&C[(size_t)(r0 + 8) * ldc + col] = make_float2(v2, v3);
        }
    }
}

__global__ __launch_bounds__(256, 2) void gemm_tf32(
    const float* __restrict__ A, int lda,
    const float* __restrict__ B, int ldb,
    float* __restrict__ C, int ldc, int K,
    const float* __restrict__ bias, int doRelu)
{
    gemm_tf32_tile(A, lda, B, ldb, C, ldc, K, bias, doRelu,
                   blockIdx.y * 128, blockIdx.x * 128);
}

// Wf = Apack @ {Wq,Wk,Wv}: one launch, grid.z selects target
__global__ __launch_bounds__(256, 2) void gemm_tf32_wf(
    const float* __restrict__ Apack,
    const float* __restrict__ Wq, const float* __restrict__ Wk,
    const float* __restrict__ Wv, float* __restrict__ Wf)
{
    int z = blockIdx.z;
    const float* B = (z == 0) ? Wq : (z == 1) ? Wk : Wv;
    gemm_tf32_tile(Apack, DIM, B, DIM, Wf + (size_t)z * DIM * DIM, DIM, DIM,
                   nullptr, 0, blockIdx.y * 128, blockIdx.x * 128);
}

// all 18 (tensor,scale) QKV GEMMs in one launch: blockIdx.z -> (t,s)
__global__ __launch_bounds__(256, 2) void gemm_tf32_qkv(
    const float* __restrict__ coeffs, const float* __restrict__ Wf,
    const float* __restrict__ biasf, float* __restrict__ QKV)
{
    int z = blockIdx.z;
    int t = z / NS, s = z % NS;
    int off = c_off[s], len = c_len[s];
    const size_t STRIDE = (size_t)BATCH * NS * DIM;
    gemm_tf32_tile(coeffs + off, DIM,
                   Wf + (size_t)t * DIM * DIM + (size_t)off * DIM, DIM,
                   QKV + (size_t)t * STRIDE + s * DIM, NS * DIM,
                   len,
                   biasf + (t * NS + s) * DIM, 0,
                   blockIdx.y * 128, blockIdx.x * 128);
}

// =====================================================================
// 4) gating
// =====================================================================
__global__ void gating_kernel(const float* __restrict__ H, const int* __restrict__ labels,
                              const float* __restrict__ W2, const float* __restrict__ b2,
                              float* __restrict__ w)
{
    int warp = threadIdx.x >> 5, lane = threadIdx.x & 31;
    int b = blockIdx.x * 8 + warp;
    if (b >= BATCH) return;
    int r = labels[b];
    const float* h  = H + (size_t)b * DIM + r * 128;
    const float* w2 = W2 + r * (HIDN * NS);
    float acc[NS] = {0, 0, 0, 0, 0, 0};
    for (int j = lane; j < HIDN; j += 32) {
        float hv = h[j];
        #pragma unroll
        for (int s = 0; s < NS; s++) acc[s] += hv * w2[j * NS + s];
    }
    #pragma unroll
    for (int s = 0; s < NS; s++)
        #pragma unroll
        for (int o = 16; o > 0; o >>= 1)
            acc[s] += __shfl_down_sync(0xffffffffu, acc[s], o);
    if (lane == 0) {
        float m = -1e30f;
        #pragma unroll
        for (int s = 0; s < NS; s++) { acc[s] += b2[r * NS + s]; m = fmaxf(m, acc[s]); }
        float sum = 0.f;
        #pragma unroll
        for (int s = 0; s < NS; s++) { acc[s] = expf(acc[s] - m); sum += acc[s]; }
        float inv = 1.f / sum;
        #pragma unroll
        for (int s = 0; s < NS; s++) w[(size_t)b * NS + s] = acc[s] * inv;
    }
}

// =====================================================================
// 5) attention + gate-weighted combine
// =====================================================================
__global__ __launch_bounds__(128) void attn_kernel(
    const float* __restrict__ Q, const float* __restrict__ K, const float* __restrict__ V,
    const float* __restrict__ w, float* __restrict__ pre)
{
    int b = blockIdx.x;
    int h = threadIdx.x >> 5, lane = threadIdx.x & 31;
    __shared__ float sq[NHEAD][NS][HD];
    __shared__ float sk[NHEAD][NS][HD];
    __shared__ float sv[NHEAD][NS][HD];
    __shared__ float att[NHEAD][NS][NS];
    __shared__ float ww[NHEAD][NS];

    size_t base = (size_t)b * (NS * DIM) + h * HD;
    #pragma unroll
    for (int s = 0; s < NS; s++)
        for (int d = lane; d < HD; d += 32) {
            sq[h][s][d] = Q[base + s * DIM + d];
            sk[h][s][d] = K[base + s * DIM + d];
            sv[h][s][d] = V[base + s * DIM + d];
        }
    __syncwarp();

    const float scale = 0.08838834764831845f;
    for (int p = lane; p < NS * NS; p += 32) {
        int i = p / NS, j = p % NS;
        float s0 = 0.f;
        #pragma unroll 8
        for (int d = 0; d < HD; d++) s0 += sq[h][i][d] * sk[h][j][d];
        att[h][i][j] = s0 * scale;
    }
    __syncwarp();
    if (lane < NS) {
        int i = lane;
        float m = -1e30f;
        #pragma unroll
        for (int j = 0; j < NS; j++) m = fmaxf(m, att[h][i][j]);
        float e[NS], sum = 0.f;
        #pragma unroll
        for (int j = 0; j < NS; j++) { e[j] = expf(att[h][i][j] - m); sum += e[j]; }
        float inv = 1.f / sum;
        #pragma unroll
        for (int j = 0; j < NS; j++) att[h][i][j] = e[j] * inv;
    }
    __syncwarp();
    if (lane < NS) {
        int j = lane;
        float t = 0.f;
        #pragma unroll
        for (int i = 0; i < NS; i++) t += w[(size_t)b * NS + i] * att[h][i][j];
        ww[h][j] = t;
    }
    __syncwarp();
    for (int d = lane; d < HD; d += 32) {
        float o = 0.f;
        #pragma unroll
        for (int j = 0; j < NS; j++) o += ww[h][j] * sv[h][j][d];
        pre[(size_t)b * DIM + h * HD + d] = o;
    }
}

// =====================================================================
// 6) residual + layernorm
// =====================================================================
__global__ __launch_bounds__(256) void ln_kernel(
    const float* __restrict__ x, const float* __restrict__ agg,
    const float* __restrict__ g, const float* __restrict__ be,
    float* __restrict__ out)
{
    int b = blockIdx.x, tid = threadIdx.x;
    __shared__ float rs[8], rq[8];
    size_t base = (size_t)b * DIM;
    float y0 = x[base + tid]       + agg[base + tid];
    float y1 = x[base + tid + 256] + agg[base + tid + 256];
    float s = y0 + y1, q = y0 * y0 + y1 * y1;
    #pragma unroll
    for (int o = 16; o > 0; o >>= 1) {
        s += __shfl_down_sync(0xffffffffu, s, o);
        q += __shfl_down_sync(0xffffffffu, q, o);
    }
    int warp = tid >> 5, lane = tid & 31;
    if (lane == 0) { rs[warp] = s; rq[warp] = q; }
    __syncthreads();
    if (tid == 0) {
        float ts = 0.f, tq = 0.f;
        #pragma unroll
        for (int i = 0; i < 8; i++) { ts += rs[i]; tq += rq[i]; }
        rs[0] = ts; rq[0] = tq;
    }
    __syncthreads();
    float mu  = rs[0] * (1.f / DIM);
    float var = rq[0] * (1.f / DIM) - mu * mu;
    float rstd = rsqrtf(var + 1e-5f);
    out[base + tid]       = (y0 - mu) * rstd * g[tid]       + be[tid];
    out[base + tid + 256] = (y1 - mu) * rstd * g[tid + 256] + be[tid + 256];
}

// =====================================================================
// host
// =====================================================================
extern "C" void kernel_launch(void* const* d_in, const int* in_sizes, int n_in,
                              void* d_out, int out_size)
{
    bool ins = (in_sizes[0] == BATCH * DIM);
    auto P = [&](int i_ins, int i_alpha) -> const float* {
        return (const float*)d_in[ins ? i_ins : i_alpha];
    };
    const float* x   = P(0, 17);
    const float* W1  = P(1, 0);
    const float* b1  = P(2, 7);
    const float* W2  = P(3, 1);
    const float* b2  = P(4, 8);
    const float* Wp  = P(5, 4);
    const float* bp  = P(6, 11);
    const float* Wq  = P(7, 5);  const float* bq = P(8, 12);
    const float* Wk  = P(9, 2);  const float* bk = P(10, 9);
    const float* Wv  = P(11, 6); const float* bv = P(12, 13);
    const float* Wo  = P(13, 3); const float* bo = P(14, 10);
    const float* lng = P(15, 15);
    const float* lnb = P(16, 14);
    const int* labels = (const int*)d_in[ins ? 17 : 16];
    float* out = (float*)d_out;

    float *coeffs, *H, *wts, *W1cat, *biasH, *Apack, *Wf, *biasf, *QKV, *pre, *agg;
    cudaGetSymbolAddress((void**)&coeffs, g_coeffs);
    cudaGetSymbolAddress((void**)&H,      g_H);
    cudaGetSymbolAddress((void**)&wts,    g_wts);
    cudaGetSymbolAddress((void**)&W1cat,  g_W1cat);
    cudaGetSymbolAddress((void**)&biasH,  g_biasH);
    cudaGetSymbolAddress((void**)&Apack,  g_Apack);
    cudaGetSymbolAddress((void**)&Wf,     g_Wf);
    cudaGetSymbolAddress((void**)&biasf,  g_biasf);
    cudaGetSymbolAddress((void**)&QKV,    g_QKV);
    cudaGetSymbolAddress((void**)&pre,    g_pre);
    cudaGetSymbolAddress((void**)&agg,    g_agg);

    const size_t QKV_STRIDE = (size_t)BATCH * NS * DIM;

    // 1. wavelet transform
    dwt_kernel<<<BATCH, 256>>>(x, coeffs);

    // 2. weight repack + fused-weight GEMMs + fused biases
    prep_pack<<<512, 512>>>(W1, b1, Wp, W1cat, biasH, Apack);
    gemm_tf32_wf<<<dim3(4, 4, 3), 256>>>(Apack, Wq, Wk, Wv, Wf);
    prep_biasf<<<18, 512>>>(bp, Wq, Wk, Wv, bq, bk, bv, biasf);

    // 3. gating: H = relu(x@W1cat + biasH), then regime select + softmax
    gemm_tf32<<<dim3(4, 64), 256>>>(x, DIM, W1cat, DIM, H, DIM, DIM, biasH, 1);
    gating_kernel<<<BATCH / 8, 256>>>(H, labels, W2, b2, wts);

    // 4. packed QKV: all 18 (tensor, scale) GEMMs in one launch
    gemm_tf32_qkv<<<dim3(4, 64, 18), 256>>>(coeffs, Wf, biasf, QKV);

    // 5. attention + gate-weighted combine (Wo folded out of the S loop)
    attn_kernel<<<BATCH, 128>>>(QKV, QKV + QKV_STRIDE, QKV + 2 * QKV_STRIDE, wts, pre);

    // 6. output projection, residual, layernorm
    gemm_tf32<<<dim3(4, 64), 256>>>(pre, DIM, Wo, DIM, agg, DIM, DIM, bo, 0);
    ln_kernel<<<BATCH, 256>>>(x, agg, lng, lnb, out);
}

// round 4
// speedup vs baseline: 2.3465x; 1.3930x over previous
#include <cuda_runtime.h>
#include <cuda_bf16.h>
#include <math.h>

#define BATCH 8192
#define DIM   512
#define NREG  4
#define NS    6
#define HIDN  128
#define NHEAD 4
#define HD    128
#define KEXT  528   // 512 coeffs + 6 ww slots + 10 pad

// db8 lowpass (pywt 'periodization')
__constant__ float c_lo[16] = {
    -0.00011747678400228192f, 0.0006754494059985568f, -0.0003917403729959771f,
    -0.00487035299301066f,    0.008746094047015655f,  0.013981027917015516f,
    -0.04408825393106472f,    -0.01736930100202211f,  0.128747426620186f,
    0.00047248457399797254f,  -0.2840155429624281f,   -0.015829105256023893f,
    0.5853546836548691f,      0.6756307362980128f,    0.3128715909144659f,
    0.05441584224308161f
};

__constant__ int c_off[NS] = {0, 16, 32, 64, 128, 256};
__constant__ int c_len[NS] = {16, 16, 32, 64, 128, 256};

// ---- scratch ----
__device__ float g_coeffs[BATCH * DIM];
__device__ float g_H[BATCH * DIM];
__device__ float g_wts[BATCH * NS];
__device__ float g_W1cat[DIM * DIM];
__device__ float g_biasH[DIM];
__device__ float g_Apack[DIM * DIM];
__device__ float g_Wf[2 * DIM * DIM];              // fused Wq, Wk
__device__ float g_Wfv[KEXT * DIM];                // fused Wv, extended with bias rows
__device__ float g_biasf[2 * NS * DIM];            // fused q,k biases
__device__ __nv_bfloat16 g_Qb[BATCH * NS * DIM];   // q bf16 (50 MB)
__device__ __nv_bfloat16 g_Kb[BATCH * NS * DIM];   // k bf16 (50 MB)
__device__ float g_cs[(size_t)BATCH * NHEAD * KEXT]; // scaled coeffs (69 MB)
__device__ float g_pre[BATCH * DIM];
__device__ float g_agg[BATCH * DIM];

// =====================================================================
// 1) DWT
// =====================================================================
__global__ void dwt_kernel(const float* __restrict__ x, float* __restrict__ coeffs)
{
    int b = blockIdx.x;
    __shared__ float buf0[DIM], buf1[DIM];
    float* cur = buf0;
    float* nxt = buf1;
    for (int d = threadIdx.x; d < DIM; d += blockDim.x)
        cur[d] = x[(size_t)b * DIM + d];
    __syncthreads();

    int n = DIM;
    #pragma unroll
    for (int lev = 0; lev < 5; lev++) {
        int nh = n >> 1;
        for (int k = threadIdx.x; k < nh; k += blockDim.x) {
            float sa = 0.f, sd = 0.f;
            #pragma unroll
            for (int j = 0; j < 16; j++) {
                int m = 2 * k + 1 - j;
                if (m < 0) m += n;
                float av = cur[m];
                float hj = c_lo[15 - j] * ((j & 1) ? 1.f : -1.f);
                sa += c_lo[j] * av;
                sd += hj * av;
            }
            nxt[k] = sa;
            coeffs[(size_t)b * DIM + nh + k] = sd;
        }
        __syncthreads();
        float* t = cur; cur = nxt; nxt = t;
        n = nh;
    }
    for (int k = threadIdx.x; k < 16; k += blockDim.x)
        coeffs[(size_t)b * DIM + k] = cur[k];
}

// =====================================================================
// 2) weight repacking
// =====================================================================
__global__ void prep_pack(const float* __restrict__ W1, const float* __restrict__ b1,
                          const float* __restrict__ Wp,
                          float* __restrict__ W1cat, float* __restrict__ biasH,
                          float* __restrict__ Apack, float* __restrict__ Wfv)
{
    int row = blockIdx.x;
    int c   = threadIdx.x;
    int r = c >> 7, j = c & 127;
    W1cat[row * DIM + c] = W1[r * (516 * 128) + row * 128 + j];

    int s, k;
    if      (row < 16)  { s = 0; k = row;       }
    else if (row < 32)  { s = 1; k = row - 16;  }
    else if (row < 64)  { s = 2; k = row - 32;  }
    else if (row < 128) { s = 3; k = row - 64;  }
    else if (row < 256) { s = 4; k = row - 128; }
    else                { s = 5; k = row - 256; }
    Apack[row * DIM + c] = Wp[s * (DIM * DIM) + k * DIM + c];

    if (row == 0)
        biasH[c] = b1[r * 128 + j] + W1[r * (516 * 128) + (512 + r) * 128 + j];
    if (row < KEXT - 518)   // zero pad rows 518..527 of Wfv_ext
        Wfv[(518 + row) * DIM + c] = 0.f;
}

// biasf for q,k (z=0..11) and Wfv_ext bias rows (z=12..17)
// out[d] = bp[s] @ W[:, d] + bvec[d]
__global__ void prep_bias(const float* __restrict__ bp,
                          const float* __restrict__ Wq, const float* __restrict__ Wk,
                          const float* __restrict__ Wv,
                          const float* __restrict__ bq, const float* __restrict__ bk,
                          const float* __restrict__ bv,
                          float* __restrict__ biasf, float* __restrict__ Wfv)
{
    int z = blockIdx.x;                 // 0..17
    int t = z / NS, s = z % NS;
    int d = blockIdx.y * 128 + threadIdx.x;
    const float* W    = (t == 0) ? Wq : (t == 1) ? Wk : Wv;
    const float* bvec = (t == 0) ? bq : (t == 1) ? bk : bv;
    const float* b    = bp + s * DIM;
    float a0 = 0.f, a1 = 0.f, a2 = 0.f, a3 = 0.f;
    #pragma unroll 2
    for (int e = 0; e < DIM; e += 8) {
        a0 += b[e + 0] * W[(e + 0) * DIM + d] + b[e + 4] * W[(e + 4) * DIM + d];
        a1 += b[e + 1] * W[(e + 1) * DIM + d] + b[e + 5] * W[(e + 5) * DIM + d];
        a2 += b[e + 2] * W[(e + 2) * DIM + d] + b[e + 6] * W[(e + 6) * DIM + d];
        a3 += b[e + 3] * W[(e + 3) * DIM + d] + b[e + 7] * W[(e + 7) * DIM + d];
    }
    float r = a0 + a1 + a2 + a3 + bvec[d];
    if (t < 2) biasf[(t * NS + s) * DIM + d] = r;
    else       Wfv[(512 + s) * DIM + d] = r;
}

// =====================================================================
// 3) tf32 tensor-core GEMM, cp.async double-buffered
//    128x128 tile, BK=16, 8 warps, mma.m16n8k8, raw-fp32-as-tf32
// =====================================================================
__device__ __forceinline__ void cp16(void* dst, const void* src) {
    unsigned d = (unsigned)__cvta_generic_to_shared(dst);
    asm volatile("cp.async.ca.shared.global [%0], [%1], 16;" :: "r"(d), "l"(src));
}

__device__ __forceinline__ void gemm_tile(
    const float* __restrict__ A, int lda,
    const float* __restrict__ B, int ldb,
    float* __restrict__ C, __nv_bfloat16* __restrict__ Cb, int ldc, int K,
    const float* __restrict__ bias, int doRelu,
    int bm, int bn)
{
    __shared__ float As[2][128][20];
    __shared__ float Bs[2][16][136];
    int t = threadIdx.x;
    int warp = t >> 5, lane = t & 31;
    int wm = (warp >> 2) * 64;
    int wn = (warp & 3) * 32;
    int gid = lane >> 2, tig = lane & 3;

    int aRow = t >> 2, aC = (t & 3) << 2;
    int bRow = t >> 5, bC = (t & 31) << 2;
    const float* Ab = A + (size_t)bm * lda;
    int nk = K >> 4;

    cp16(&As[0][aRow][aC],      &Ab[(size_t)aRow * lda + aC]);
    cp16(&As[0][aRow + 64][aC], &Ab[(size_t)(aRow + 64) * lda + aC]);
    cp16(&Bs[0][bRow][bC],      &B[(size_t)bRow * ldb + bn + bC]);
    cp16(&Bs[0][bRow + 8][bC],  &B[(size_t)(bRow + 8) * ldb + bn + bC]);
    asm volatile("cp.async.commit_group;");

    float c[4][4][4] = {};

    for (int i = 0; i < nk; i++) {
        if (i + 1 < nk) {
            int st = (i + 1) & 1, k0 = (i + 1) << 4;
            cp16(&As[st][aRow][aC],      &Ab[(size_t)aRow * lda + k0 + aC]);
            cp16(&As[st][aRow + 64][aC], &Ab[(size_t)(aRow + 64) * lda + k0 + aC]);
            cp16(&Bs[st][bRow][bC],      &B[(size_t)(k0 + bRow) * ldb + bn + bC]);
            cp16(&Bs[st][bRow + 8][bC],  &B[(size_t)(k0 + bRow + 8) * ldb + bn + bC]);
            asm volatile("cp.async.commit_group;");
            asm volatile("cp.async.wait_group 1;");
        } else {
            asm volatile("cp.async.wait_group 0;");
        }
        __syncthreads();
        int st = i & 1;
        #pragma unroll
        for (int kk = 0; kk < 16; kk += 8) {
            unsigned a[4][4], b[4][2];
            #pragma unroll
            for (int mi = 0; mi < 4; mi++) {
                const float* p = &As[st][wm + mi * 16 + gid][kk + tig];
                a[mi][0] = __float_as_uint(p[0]);
                a[mi][1] = __float_as_uint(p[8 * 20]);
                a[mi][2] = __float_as_uint(p[4]);
                a[mi][3] = __float_as_uint(p[8 * 20 + 4]);
            }
            #pragma unroll
            for (int ni = 0; ni < 4; ni++) {
                const float* p = &Bs[st][kk + tig][wn + ni * 8 + gid];
                b[ni][0] = __float_as_uint(p[0]);
                b[ni][1] = __float_as_uint(p[4 * 136]);
            }
            #pragma unroll
            for (int mi = 0; mi < 4; mi++)
                #pragma unroll
                for (int ni = 0; ni < 4; ni++)
                    asm volatile(
                        "mma.sync.aligned.m16n8k8.row.col.f32.tf32.tf32.f32 "
                        "{%0,%1,%2,%3}, {%4,%5,%6,%7}, {%8,%9}, {%0,%1,%2,%3};"
                        : "+f"(c[mi][ni][0]), "+f"(c[mi][ni][1]),
                          "+f"(c[mi][ni][2]), "+f"(c[mi][ni][3])
                        : "r"(a[mi][0]), "r"(a[mi][1]), "r"(a[mi][2]), "r"(a[mi][3]),
                          "r"(b[ni][0]), "r"(b[ni][1]));
        }
        __syncthreads();
    }

    #pragma unroll
    for (int mi = 0; mi < 4; mi++) {
        int r0 = bm + wm + mi * 16 + gid;
        #pragma unroll
        for (int ni = 0; ni < 4; ni++) {
            int col = bn + wn + ni * 8 + tig * 2;
            float b0 = 0.f, b1 = 0.f;
            if (bias) { b0 = bias[col]; b1 = bias[col + 1]; }
            float v0 = c[mi][ni][0] + b0, v1 = c[mi][ni][1] + b1;
            float v2 = c[mi][ni][2] + b0, v3 = c[mi][ni][3] + b1;
            if (doRelu) {
                v0 = fmaxf(v0, 0.f); v1 = fmaxf(v1, 0.f);
                v2 = fmaxf(v2, 0.f); v3 = fmaxf(v3, 0.f);
            }
            if (Cb) {
                *(__nv_bfloat162*)&Cb[(size_t)r0 * ldc + col] =
                    __floats2bfloat162_rn(v0, v1);
                *(__nv_bfloat162*)&Cb[(size_t)(r0 + 8) * ldc + col] =
                    __floats2bfloat162_rn(v2, v3);
            } else {
                *(float2*)&C[(size_t)r0 * ldc + col]       = make_float2(v0, v1);
                *(float2*)&C[(size_t)(r0 + 8) * ldc + col] = make_float2(v2, v3);
            }
        }
    }
}

__global__ __launch_bounds__(256, 2) void gemm_tf32(
    const float* __restrict__ A, int lda,
    const float* __restrict__ B, int ldb,
    float* __restrict__ C, int ldc, int K,
    const float* __restrict__ bias, int doRelu)
{
    gemm_tile(A, lda, B, ldb, C, nullptr, ldc, K, bias, doRelu,
              blockIdx.y * 128, blockIdx.x * 128);
}

// Wfq = Apack@Wq, Wfk = Apack@Wk, Wfv = Apack@Wv (rows 0..511 of g_Wfv)
__global__ __launch_bounds__(256, 2) void gemm_wf(
    const float* __restrict__ Apack,
    const float* __restrict__ Wq, const float* __restrict__ Wk,
    const float* __restrict__ Wv, float* __restrict__ Wf, float* __restrict__ Wfv)
{
    int z = blockIdx.z;
    const float* B = (z == 0) ? Wq : (z == 1) ? Wk : Wv;
    float* C = (z == 2) ? Wfv : Wf + (size_t)z * DIM * DIM;
    gemm_tile(Apack, DIM, B, DIM, C, nullptr, DIM, DIM, nullptr, 0,
              blockIdx.y * 128, blockIdx.x * 128);
}

// q,k slices -> bf16: z in 0..11 -> (t, s)
__global__ __launch_bounds__(256, 2) void gemm_qk(
    const float* __restrict__ coeffs, const float* __restrict__ Wf,
    const float* __restrict__ biasf,
    __nv_bfloat16* __restrict__ Qb, __nv_bfloat16* __restrict__ Kb)
{
    int z = blockIdx.z;
    int t = z / NS, s = z % NS;
    int off = c_off[s], len = c_len[s];
    __nv_bfloat16* Cb = (t == 0 ? Qb : Kb) + s * DIM;
    gemm_tile(coeffs + off, DIM,
              Wf + (size_t)t * DIM * DIM + (size_t)off * DIM, DIM,
              nullptr, Cb, NS * DIM, len,
              biasf + (t * NS + s) * DIM, 0,
              blockIdx.y * 128, blockIdx.x * 128);
}

// pre[:, h*128:(h+1)*128] = cs_h @ Wfv_ext[:, h*128:...], K=528
__global__ __launch_bounds__(256, 2) void gemm_vpre(
    const float* __restrict__ cs, const float* __restrict__ Wfv,
    float* __restrict__ pre)
{
    int h = blockIdx.z;
    gemm_tile(cs + (size_t)h * KEXT, NHEAD * KEXT,
              Wfv + h * HD, DIM,
              pre + h * HD, nullptr, DIM, KEXT,
              nullptr, 0,
              blockIdx.y * 128, 0);
}

// =====================================================================
// 4) gating
// =====================================================================
__global__ void gating_kernel(const float* __restrict__ H, const int* __restrict__ labels,
                              const float* __restrict__ W2, const float* __restrict__ b2,
                              float* __restrict__ w)
{
    int warp = threadIdx.x >> 5, lane = threadIdx.x & 31;
    int b = blockIdx.x * 8 + warp;
    if (b >= BATCH) return;
    int r = labels[b];
    const float* h  = H + (size_t)b * DIM + r * 128;
    const float* w2 = W2 + r * (HIDN * NS);
    float acc[NS] = {0, 0, 0, 0, 0, 0};
    for (int j = lane; j < HIDN; j += 32) {
        float hv = h[j];
        #pragma unroll
        for (int s = 0; s < NS; s++) acc[s] += hv * w2[j * NS + s];
    }
    #pragma unroll
    for (int s = 0; s < NS; s++)
        #pragma unroll
        for (int o = 16; o > 0; o >>= 1)
            acc[s] += __shfl_down_sync(0xffffffffu, acc[s], o);
    if (lane == 0) {
        float m = -1e30f;
        #pragma unroll
        for (int s = 0; s < NS; s++) { acc[s] += b2[r * NS + s]; m = fmaxf(m, acc[s]); }
        float sum = 0.f;
        #pragma unroll
        for (int s = 0; s < NS; s++) { acc[s] = expf(acc[s] - m); sum += acc[s]; }
        float inv = 1.f / sum;
        #pragma unroll
        for (int s = 0; s < NS; s++) w[(size_t)b * NS + s] = acc[s] * inv;
    }
}

// =====================================================================
// 5) scores -> softmax -> per-head combine weights -> scaled coeffs cs
//    one block (4 warps = 1/head) per batch row
// =====================================================================
__global__ __launch_bounds__(128) void score_kernel(
    const __nv_bfloat16* __restrict__ Qb, const __nv_bfloat16* __restrict__ Kb,
    const float* __restrict__ coeffs, const float* __restrict__ wts,
    float* __restrict__ cs)
{
    int b = blockIdx.x;
    int h = threadIdx.x >> 5, lane = threadIdx.x & 31;
    int t = threadIdx.x;
    __shared__ __nv_bfloat16 sq[NS * DIM];
    __shared__ __nv_bfloat16 sk[NS * DIM];
    __shared__ float sco[DIM];
    __shared__ float wg[NS];
    __shared__ float att[NHEAD][NS][NS];
    __shared__ float ww[NHEAD][NS];

    const uint4* qs = (const uint4*)(Qb + (size_t)b * NS * DIM);
    const uint4* ks = (const uint4*)(Kb + (size_t)b * NS * DIM);
    uint4* qd = (uint4*)sq;
    uint4* kd = (uint4*)sk;
    #pragma unroll
    for (int i = 0; i < 3; i++) {
        qd[t + i * 128] = qs[t + i * 128];
        kd[t + i * 128] = ks[t + i * 128];
    }
    ((float4*)sco)[t] = ((const float4*)(coeffs + (size_t)b * DIM))[t];
    if (t < NS) wg[t] = wts[(size_t)b * NS + t];
    __syncthreads();

    // scores for head h: 36 (i,j) dot products of 128 dims
    const __nv_bfloat162* q2 = (const __nv_bfloat162*)sq + h * 64;
    const __nv_bfloat162* k2 = (const __nv_bfloat162*)sk + h * 64;
    const float scale = 0.08838834764831845f;
    for (int p = lane; p < NS * NS; p += 32) {
        int i = p / NS, j = p % NS;
        const __nv_bfloat162* qi = q2 + i * 256;
        const __nv_bfloat162* kj = k2 + j * 256;
        float s0 = 0.f;
        #pragma unroll 16
        for (int d = 0; d < 64; d++) {
            float2 qa = __bfloat1622float2(qi[d]);
            float2 kb = __bfloat1622float2(kj[d]);
            s0 += qa.x * kb.x + qa.y * kb.y;
        }
        att[h][i][j] = s0 * scale;
    }
    __syncwarp();
    if (lane < NS) {
        int i = lane;
        float m = -1e30f;
        #pragma unroll
        for (int j = 0; j < NS; j++) m = fmaxf(m, att[h][i][j]);
        float e[NS], sum = 0.f;
        #pragma unroll
        for (int j = 0; j < NS; j++) { e[j] = expf(att[h][i][j] - m); sum += e[j]; }
        float inv = 1.f / sum;
        #pragma unroll
        for (int j = 0; j < NS; j++) att[h][i][j] = e[j] * inv;
    }
    __syncwarp();
    if (lane < NS) {
        int j = lane;
        float s = 0.f;
        #pragma unroll
        for (int i = 0; i < NS; i++) s += wg[i] * att[h][i][j];
        ww[h][j] = s;
    }
    __syncwarp();

    float wl[NS];
    #pragma unroll
    for (int j = 0; j < NS; j++) wl[j] = ww[h][j];

    float* crow = cs + ((size_t)b * NHEAD + h) * KEXT;
    #pragma unroll
    for (int kk = 0; kk < 16; kk++) {
        int k = kk * 32 + lane;
        int sl = (k < 16) ? 0 : (k < 32) ? 1 : (k < 64) ? 2 :
                 (k < 128) ? 3 : (k < 256) ? 4 : 5;
        crow[k] = wl[sl] * sco[k];
    }
    if (lane < 16) crow[512 + lane] = (lane < NS) ? wl[lane] : 0.f;
}

// =====================================================================
// 6) residual + layernorm
// =====================================================================
__global__ __launch_bounds__(256) void ln_kernel(
    const float* __restrict__ x, const float* __restrict__ agg,
    const float* __restrict__ g, const float* __restrict__ be,
    float* __restrict__ out)
{
    int b = blockIdx.x, tid = threadIdx.x;
    __shared__ float rs[8], rq[8];
    size_t base = (size_t)b * DIM;
    float y0 = x[base + tid]       + agg[base + tid];
    float y1 = x[base + tid + 256] + agg[base + tid + 256];
    float s = y0 + y1, q = y0 * y0 + y1 * y1;
    #pragma unroll
    for (int o = 16; o > 0; o >>= 1) {
        s += __shfl_down_sync(0xffffffffu, s, o);
        q += __shfl_down_sync(0xffffffffu, q, o);
    }
    int warp = tid >> 5, lane = tid & 31;
    if (lane == 0) { rs[warp] = s; rq[warp] = q; }
    __syncthreads();
    if (tid == 0) {
        float ts = 0.f, tq = 0.f;
        #pragma unroll
        for (int i = 0; i < 8; i++) { ts += rs[i]; tq += rq[i]; }
        rs[0] = ts; rq[0] = tq;
    }
    __syncthreads();
    float mu  = rs[0] * (1.f / DIM);
    float var = rq[0] * (1.f / DIM) - mu * mu;
    float rstd = rsqrtf(var + 1e-5f);
    out[base + tid]       = (y0 - mu) * rstd * g[tid]       + be[tid];
    out[base + tid + 256] = (y1 - mu) * rstd * g[tid + 256] + be[tid + 256];
}

// =====================================================================
// host
// =====================================================================
extern "C" void kernel_launch(void* const* d_in, const int* in_sizes, int n_in,
                              void* d_out, int out_size)
{
    bool ins = (in_sizes[0] == BATCH * DIM);
    auto P = [&](int i_ins, int i_alpha) -> const float* {
        return (const float*)d_in[ins ? i_ins : i_alpha];
    };
    const float* x   = P(0, 17);
    const float* W1  = P(1, 0);
    const float* b1  = P(2, 7);
    const float* W2  = P(3, 1);
    const float* b2  = P(4, 8);
    const float* Wp  = P(5, 4);
    const float* bp  = P(6, 11);
    const float* Wq  = P(7, 5);  const float* bq = P(8, 12);
    const float* Wk  = P(9, 2);  const float* bk = P(10, 9);
    const float* Wv  = P(11, 6); const float* bv = P(12, 13);
    const float* Wo  = P(13, 3); const float* bo = P(14, 10);
    const float* lng = P(15, 15);
    const float* lnb = P(16, 14);
    const int* labels = (const int*)d_in[ins ? 17 : 16];
    float* out = (float*)d_out;

    float *coeffs, *H, *wts, *W1cat, *biasH, *Apack, *Wf, *Wfv, *biasf, *cs, *pre, *agg;
    __nv_bfloat16 *Qb, *Kb;
    cudaGetSymbolAddress((void**)&coeffs, g_coeffs);
    cudaGetSymbolAddress((void**)&H,      g_H);
    cudaGetSymbolAddress((void**)&wts,    g_wts);
    cudaGetSymbolAddress((void**)&W1cat,  g_W1cat);
    cudaGetSymbolAddress((void**)&biasH,  g_biasH);
    cudaGetSymbolAddress((void**)&Apack,  g_Apack);
    cudaGetSymbolAddress((void**)&Wf,     g_Wf);
    cudaGetSymbolAddress((void**)&Wfv,    g_Wfv);
    cudaGetSymbolAddress((void**)&biasf,  g_biasf);
    cudaGetSymbolAddress((void**)&Qb,     g_Qb);
    cudaGetSymbolAddress((void**)&Kb,     g_Kb);
    cudaGetSymbolAddress((void**)&cs,     g_cs);
    cudaGetSymbolAddress((void**)&pre,    g_pre);
    cudaGetSymbolAddress((void**)&agg,    g_agg);

    // 1. wavelet transform
    dwt_kernel<<<BATCH, 256>>>(x, coeffs);

    // 2. weight repack + fused-weight GEMMs + fused biases
    prep_pack<<<512, 512>>>(W1, b1, Wp, W1cat, biasH, Apack, Wfv);
    gemm_wf<<<dim3(4, 4, 3), 256>>>(Apack, Wq, Wk, Wv, Wf, Wfv);
    prep_bias<<<dim3(18, 4), 128>>>(bp, Wq, Wk, Wv, bq, bk, bv, biasf, Wfv);

    // 3. gating: H = relu(x@W1cat + biasH) -> regime select + softmax
    gemm_tf32<<<dim3(4, 64), 256>>>(x, DIM, W1cat, DIM, H, DIM, DIM, biasH, 1);
    gating_kernel<<<BATCH / 8, 256>>>(H, labels, W2, b2, wts);

    // 4. q,k in bf16 (12 slice-GEMMs, one launch)
    gemm_qk<<<dim3(4, 64, 12), 256>>>(coeffs, Wf, biasf, Qb, Kb);

    // 5. scores + softmax + gate combine -> scaled coefficients
    score_kernel<<<BATCH, 128>>>(Qb, Kb, coeffs, wts, cs);

    // 6. pre = cs_h @ Wfv_ext (V never materialized; V-bias rides in K-rows 512..517)
    gemm_vpre<<<dim3(1, 64, 4), 256>>>(cs, Wfv, pre);

    // 7. output projection + residual + layernorm
    gemm_tf32<<<dim3(4, 64), 256>>>(pre, DIM, Wo, DIM, agg, DIM, DIM, bo, 0);
    ln_kernel<<<BATCH, 256>>>(x, agg, lng, lnb, out);
}

// round 5
// speedup vs baseline: 2.9349x; 1.2507x over previous
#include <cuda_runtime.h>
#include <cuda_bf16.h>
#include <math.h>

#define BATCH 8192
#define DIM   512
#define NREG  4
#define NS    6
#define HIDN  128
#define NHEAD 4
#define HD    128
#define KEXT  528   // 512 coeffs + 6 ww slots + 10 pad

// db8 lowpass (pywt 'periodization')
__constant__ float c_lo[16] = {
    -0.00011747678400228192f, 0.0006754494059985568f, -0.0003917403729959771f,
    -0.00487035299301066f,    0.008746094047015655f,  0.013981027917015516f,
    -0.04408825393106472f,    -0.01736930100202211f,  0.128747426620186f,
    0.00047248457399797254f,  -0.2840155429624281f,   -0.015829105256023893f,
    0.5853546836548691f,      0.6756307362980128f,    0.3128715909144659f,
    0.05441584224308161f
};

__constant__ int c_off[NS] = {0, 16, 32, 64, 128, 256};
__constant__ int c_len[NS] = {16, 16, 32, 64, 128, 256};

// ---- scratch ----
__device__ float g_coeffs[BATCH * DIM];
__device__ __nv_bfloat16 g_coeffsb[BATCH * DIM];
__device__ float g_H[BATCH * DIM];
__device__ float g_wts[BATCH * NS];
__device__ float g_W1cat[DIM * DIM];
__device__ float g_biasH[DIM];
__device__ float g_Apack[DIM * DIM];
__device__ float g_Wf[2 * DIM * DIM];               // fused Wq, Wk (fp32)
__device__ __nv_bfloat16 g_WfT[2 * DIM * DIM];      // transposed bf16 [n][k]
__device__ float g_Wfv[KEXT * DIM];                 // fused Wv + bias rows
__device__ float g_biasf[2 * NS * DIM];
__device__ float g_bias_part[8 * 18 * DIM];         // split-K partials
__device__ __nv_bfloat16 g_Qb[BATCH * NS * DIM];
__device__ __nv_bfloat16 g_Kb[BATCH * NS * DIM];
__device__ float g_cs[(size_t)BATCH * NHEAD * KEXT];
__device__ float g_pre[BATCH * DIM];
__device__ float g_agg[BATCH * DIM];

// =====================================================================
// 1) DWT (emits fp32 + bf16 copies)
// =====================================================================
__global__ void dwt_kernel(const float* __restrict__ x, float* __restrict__ coeffs,
                           __nv_bfloat16* __restrict__ coeffsb)
{
    int b = blockIdx.x;
    __shared__ float buf0[DIM], buf1[DIM];
    float* cur = buf0;
    float* nxt = buf1;
    for (int d = threadIdx.x; d < DIM; d += blockDim.x)
        cur[d] = x[(size_t)b * DIM + d];
    __syncthreads();

    int n = DIM;
    #pragma unroll
    for (int lev = 0; lev < 5; lev++) {
        int nh = n >> 1;
        for (int k = threadIdx.x; k < nh; k += blockDim.x) {
            float sa = 0.f, sd = 0.f;
            #pragma unroll
            for (int j = 0; j < 16; j++) {
                int m = 2 * k + 1 - j;
                if (m < 0) m += n;
                float av = cur[m];
                float hj = c_lo[15 - j] * ((j & 1) ? 1.f : -1.f);
                sa += c_lo[j] * av;
                sd += hj * av;
            }
            nxt[k] = sa;
            coeffs[(size_t)b * DIM + nh + k]  = sd;
            coeffsb[(size_t)b * DIM + nh + k] = __float2bfloat16(sd);
        }
        __syncthreads();
        float* t = cur; cur = nxt; nxt = t;
        n = nh;
    }
    for (int k = threadIdx.x; k < 16; k += blockDim.x) {
        coeffs[(size_t)b * DIM + k]  = cur[k];
        coeffsb[(size_t)b * DIM + k] = __float2bfloat16(cur[k]);
    }
}

// =====================================================================
// 2) weight repacking
// =====================================================================
__global__ void prep_pack(const float* __restrict__ W1, const float* __restrict__ b1,
                          const float* __restrict__ Wp,
                          float* __restrict__ W1cat, float* __restrict__ biasH,
                          float* __restrict__ Apack, float* __restrict__ Wfv)
{
    int row = blockIdx.x;
    int c   = threadIdx.x;
    int r = c >> 7, j = c & 127;
    W1cat[row * DIM + c] = W1[r * (516 * 128) + row * 128 + j];

    int s, k;
    if      (row < 16)  { s = 0; k = row;       }
    else if (row < 32)  { s = 1; k = row - 16;  }
    else if (row < 64)  { s = 2; k = row - 32;  }
    else if (row < 128) { s = 3; k = row - 64;  }
    else if (row < 256) { s = 4; k = row - 128; }
    else                { s = 5; k = row - 256; }
    Apack[row * DIM + c] = Wp[s * (DIM * DIM) + k * DIM + c];

    if (row == 0)
        biasH[c] = b1[r * 128 + j] + W1[r * (516 * 128) + (512 + r) * 128 + j];
    if (row < KEXT - 518)   // zero pad rows 518..527 of Wfv_ext
        Wfv[(518 + row) * DIM + c] = 0.f;
}

// split-K bias partials: part[ez][z][d] = sum_{e in segment} bp[s][e]*W[e][d]
__global__ void prep_bias_part(const float* __restrict__ bp,
                               const float* __restrict__ Wq, const float* __restrict__ Wk,
                               const float* __restrict__ Wv, float* __restrict__ part)
{
    int z = blockIdx.x;                 // 0..17: t*6+s
    int t = z / NS, s = z % NS;
    int d = blockIdx.y * 128 + threadIdx.x;
    int e0 = blockIdx.z * 64;
    const float* W = (t == 0) ? Wq : (t == 1) ? Wk : Wv;
    const float* b = bp + s * DIM + e0;
    const float* Wc = W + (size_t)e0 * DIM + d;
    float a = 0.f;
    #pragma unroll
    for (int e = 0; e < 64; e++)
        a += b[e] * Wc[(size_t)e * DIM];
    part[(blockIdx.z * 18 + z) * DIM + d] = a;
}

// deterministic reduce + bias add
__global__ void prep_bias_red(const float* __restrict__ part,
                              const float* __restrict__ bq, const float* __restrict__ bk,
                              const float* __restrict__ bv,
                              float* __restrict__ biasf, float* __restrict__ Wfv)
{
    int z = blockIdx.x;
    int t = z / NS, s = z % NS;
    int d = blockIdx.y * 128 + threadIdx.x;
    float a = 0.f;
    #pragma unroll
    for (int i = 0; i < 8; i++)
        a += part[(i * 18 + z) * DIM + d];
    const float* bvec = (t == 0) ? bq : (t == 1) ? bk : bv;
    a += bvec[d];
    if (t < 2) biasf[(t * NS + s) * DIM + d] = a;
    else       Wfv[(512 + s) * DIM + d] = a;
}

// tiled transpose + bf16 convert: WfT[t][n][k] = bf16(Wf[t][k][n])
__global__ void transp_bf16(const float* __restrict__ Wf, __nv_bfloat16* __restrict__ WfT)
{
    int t = blockIdx.z;
    __shared__ float tile[32][33];
    int k0 = blockIdx.y * 32, n0 = blockIdx.x * 32;
    const float* src = Wf + (size_t)t * DIM * DIM;
    __nv_bfloat16* dst = WfT + (size_t)t * DIM * DIM;
    for (int i = threadIdx.y; i < 32; i += 8)
        tile[i][threadIdx.x] = src[(size_t)(k0 + i) * DIM + n0 + threadIdx.x];
    __syncthreads();
    for (int i = threadIdx.y; i < 32; i += 8)
        dst[(size_t)(n0 + i) * DIM + k0 + threadIdx.x] =
            __float2bfloat16(tile[threadIdx.x][i]);
}

// =====================================================================
// 3) tf32 tensor-core GEMM, cp.async double-buffered
// =====================================================================
__device__ __forceinline__ void cp16(void* dst, const void* src) {
    unsigned d = (unsigned)__cvta_generic_to_shared(dst);
    asm volatile("cp.async.ca.shared.global [%0], [%1], 16;" :: "r"(d), "l"(src));
}

__device__ __forceinline__ void gemm_tile(
    const float* __restrict__ A, int lda,
    const float* __restrict__ B, int ldb,
    float* __restrict__ C, __nv_bfloat16* __restrict__ Cb, int ldc, int K,
    const float* __restrict__ bias, int doRelu,
    int bm, int bn)
{
    __shared__ float As[2][128][20];
    __shared__ float Bs[2][16][136];
    int t = threadIdx.x;
    int warp = t >> 5, lane = t & 31;
    int wm = (warp >> 2) * 64;
    int wn = (warp & 3) * 32;
    int gid = lane >> 2, tig = lane & 3;

    int aRow = t >> 2, aC = (t & 3) << 2;
    int bRow = t >> 5, bC = (t & 31) << 2;
    const float* Ab = A + (size_t)bm * lda;
    int nk = K >> 4;

    cp16(&As[0][aRow][aC],      &Ab[(size_t)aRow * lda + aC]);
    cp16(&As[0][aRow + 64][aC], &Ab[(size_t)(aRow + 64) * lda + aC]);
    cp16(&Bs[0][bRow][bC],      &B[(size_t)bRow * ldb + bn + bC]);
    cp16(&Bs[0][bRow + 8][bC],  &B[(size_t)(bRow + 8) * ldb + bn + bC]);
    asm volatile("cp.async.commit_group;");

    float c[4][4][4] = {};

    for (int i = 0; i < nk; i++) {
        if (i + 1 < nk) {
            int st = (i + 1) & 1, k0 = (i + 1) << 4;
            cp16(&As[st][aRow][aC],      &Ab[(size_t)aRow * lda + k0 + aC]);
            cp16(&As[st][aRow + 64][aC], &Ab[(size_t)(aRow + 64) * lda + k0 + aC]);
            cp16(&Bs[st][bRow][bC],      &B[(size_t)(k0 + bRow) * ldb + bn + bC]);
            cp16(&Bs[st][bRow + 8][bC],  &B[(size_t)(k0 + bRow + 8) * ldb + bn + bC]);
            asm volatile("cp.async.commit_group;");
            asm volatile("cp.async.wait_group 1;");
        } else {
            asm volatile("cp.async.wait_group 0;");
        }
        __syncthreads();
        int st = i & 1;
        #pragma unroll
        for (int kk = 0; kk < 16; kk += 8) {
            unsigned a[4][4], b[4][2];
            #pragma unroll
            for (int mi = 0; mi < 4; mi++) {
                const float* p = &As[st][wm + mi * 16 + gid][kk + tig];
                a[mi][0] = __float_as_uint(p[0]);
                a[mi][1] = __float_as_uint(p[8 * 20]);
                a[mi][2] = __float_as_uint(p[4]);
                a[mi][3] = __float_as_uint(p[8 * 20 + 4]);
            }
            #pragma unroll
            for (int ni = 0; ni < 4; ni++) {
                const float* p = &Bs[st][kk + tig][wn + ni * 8 + gid];
                b[ni][0] = __float_as_uint(p[0]);
                b[ni][1] = __float_as_uint(p[4 * 136]);
            }
            #pragma unroll
            for (int mi = 0; mi < 4; mi++)
                #pragma unroll
                for (int ni = 0; ni < 4; ni++)
                    asm volatile(
                        "mma.sync.aligned.m16n8k8.row.col.f32.tf32.tf32.f32 "
                        "{%0,%1,%2,%3}, {%4,%5,%6,%7}, {%8,%9}, {%0,%1,%2,%3};"
                        : "+f"(c[mi][ni][0]), "+f"(c[mi][ni][1]),
                          "+f"(c[mi][ni][2]), "+f"(c[mi][ni][3])
                        : "r"(a[mi][0]), "r"(a[mi][1]), "r"(a[mi][2]), "r"(a[mi][3]),
                          "r"(b[ni][0]), "r"(b[ni][1]));
        }
        __syncthreads();
    }

    #pragma unroll
    for (int mi = 0; mi < 4; mi++) {
        int r0 = bm + wm + mi * 16 + gid;
        #pragma unroll
        for (int ni = 0; ni < 4; ni++) {
            int col = bn + wn + ni * 8 + tig * 2;
            float b0 = 0.f, b1 = 0.f;
            if (bias) { b0 = bias[col]; b1 = bias[col + 1]; }
            float v0 = c[mi][ni][0] + b0, v1 = c[mi][ni][1] + b1;
            float v2 = c[mi][ni][2] + b0, v3 = c[mi][ni][3] + b1;
            if (doRelu) {
                v0 = fmaxf(v0, 0.f); v1 = fmaxf(v1, 0.f);
                v2 = fmaxf(v2, 0.f); v3 = fmaxf(v3, 0.f);
            }
            if (Cb) {
                *(__nv_bfloat162*)&Cb[(size_t)r0 * ldc + col] =
                    __floats2bfloat162_rn(v0, v1);
                *(__nv_bfloat162*)&Cb[(size_t)(r0 + 8) * ldc + col] =
                    __floats2bfloat162_rn(v2, v3);
            } else {
                *(float2*)&C[(size_t)r0 * ldc + col]       = make_float2(v0, v1);
                *(float2*)&C[(size_t)(r0 + 8) * ldc + col] = make_float2(v2, v3);
            }
        }
    }
}

__global__ __launch_bounds__(256, 2) void gemm_tf32(
    const float* __restrict__ A, int lda,
    const float* __restrict__ B, int ldb,
    float* __restrict__ C, int ldc, int K,
    const float* __restrict__ bias, int doRelu)
{
    gemm_tile(A, lda, B, ldb, C, nullptr, ldc, K, bias, doRelu,
              blockIdx.y * 128, blockIdx.x * 128);
}

__global__ __launch_bounds__(256, 2) void gemm_wf(
    const float* __restrict__ Apack,
    const float* __restrict__ Wq, const float* __restrict__ Wk,
    const float* __restrict__ Wv, float* __restrict__ Wf, float* __restrict__ Wfv)
{
    int z = blockIdx.z;
    const float* B = (z == 0) ? Wq : (z == 1) ? Wk : Wv;
    float* C = (z == 2) ? Wfv : Wf + (size_t)z * DIM * DIM;
    gemm_tile(Apack, DIM, B, DIM, C, nullptr, DIM, DIM, nullptr, 0,
              blockIdx.y * 128, blockIdx.x * 128);
}

// pre[:, h*128:(h+1)*128] = cs_h @ Wfv_ext[:, h*128:...], K=528
__global__ __launch_bounds__(256, 2) void gemm_vpre(
    const float* __restrict__ cs, const float* __restrict__ Wfv,
    float* __restrict__ pre)
{
    int h = blockIdx.z;
    gemm_tile(cs + (size_t)h * KEXT, NHEAD * KEXT,
              Wfv + h * HD, DIM,
              pre + h * HD, nullptr, DIM, KEXT,
              nullptr, 0,
              blockIdx.y * 128, 0);
}

// =====================================================================
// 3b) bf16 tensor-core GEMM for q,k: mma.m16n8k16, BK=16
//     A = coeffsb [b][k], B = WfT [n][k] (both row-major over their rows)
// =====================================================================
__global__ __launch_bounds__(256, 2) void gemm_qk_bf16(
    const __nv_bfloat16* __restrict__ coeffsb, const __nv_bfloat16* __restrict__ WfT,
    const float* __restrict__ biasf,
    __nv_bfloat16* __restrict__ Qb, __nv_bfloat16* __restrict__ Kb)
{
    int z = blockIdx.z;                 // 0..11: t*6+s
    int t = z / NS, s = z % NS;
    int off = c_off[s], len = c_len[s];
    __shared__ __nv_bfloat16 As[2][128 * 24];   // [m][k], row stride 24
    __shared__ __nv_bfloat16 Bs[2][128 * 24];   // [n][k], row stride 24
    int tid = threadIdx.x, warp = tid >> 5, lane = tid & 31;
    int wm = (warp >> 2) * 64, wn = (warp & 3) * 32;
    int gid = lane >> 2, tig = lane & 3;
    int bm = blockIdx.y * 128, bn = blockIdx.x * 128;
    int lRow = tid >> 1, lSeg = (tid & 1) * 8;

    const __nv_bfloat16* Ab = coeffsb + (size_t)bm * DIM + off;
    const __nv_bfloat16* Bb = WfT + (size_t)t * DIM * DIM + (size_t)bn * DIM + off;
    int nk = len >> 4;

    cp16(&As[0][lRow * 24 + lSeg], &Ab[(size_t)lRow * DIM + lSeg]);
    cp16(&Bs[0][lRow * 24 + lSeg], &Bb[(size_t)lRow * DIM + lSeg]);
    asm volatile("cp.async.commit_group;");

    float c[4][4][4] = {};

    for (int i = 0; i < nk; i++) {
        if (i + 1 < nk) {
            int st = (i + 1) & 1, k0 = (i + 1) << 4;
            cp16(&As[st][lRow * 24 + lSeg], &Ab[(size_t)lRow * DIM + k0 + lSeg]);
            cp16(&Bs[st][lRow * 24 + lSeg], &Bb[(size_t)lRow * DIM + k0 + lSeg]);
            asm volatile("cp.async.commit_group;");
            asm volatile("cp.async.wait_group 1;");
        } else {
            asm volatile("cp.async.wait_group 0;");
        }
        __syncthreads();
        int st = i & 1;
        unsigned a[4][4], bfr[4][2];
        #pragma unroll
        for (int mi = 0; mi < 4; mi++) {
            const __nv_bfloat16* p = &As[st][(wm + mi * 16 + gid) * 24 + 2 * tig];
            a[mi][0] = *(const unsigned*)p;             // (row gid,   k 2tig..+1)
            a[mi][1] = *(const unsigned*)(p + 8 * 24);  // (row gid+8, k 2tig..+1)
            a[mi][2] = *(const unsigned*)(p + 8);       // (row gid,   k 2tig+8..+9)
            a[mi][3] = *(const unsigned*)(p + 8 * 24 + 8);
        }
        #pragma unroll
        for (int ni = 0; ni < 4; ni++) {
            const __nv_bfloat16* p = &Bs[st][(wn + ni * 8 + gid) * 24 + 2 * tig];
            bfr[ni][0] = *(const unsigned*)p;
            bfr[ni][1] = *(const unsigned*)(p + 8);
        }
        #pragma unroll
        for (int mi = 0; mi < 4; mi++)
            #pragma unroll
            for (int ni = 0; ni < 4; ni++)
                asm volatile(
                    "mma.sync.aligned.m16n8k16.row.col.f32.bf16.bf16.f32 "
                    "{%0,%1,%2,%3}, {%4,%5,%6,%7}, {%8,%9}, {%0,%1,%2,%3};"
                    : "+f"(c[mi][ni][0]), "+f"(c[mi][ni][1]),
                      "+f"(c[mi][ni][2]), "+f"(c[mi][ni][3])
                    : "r"(a[mi][0]), "r"(a[mi][1]), "r"(a[mi][2]), "r"(a[mi][3]),
                      "r"(bfr[ni][0]), "r"(bfr[ni][1]));
        __syncthreads();
    }

    __nv_bfloat16* Cb = (t == 0 ? Qb : Kb) + s * DIM;
    const float* bias = biasf + (t * NS + s) * DIM;
    const int ldc = NS * DIM;
    #pragma unroll
    for (int mi = 0; mi < 4; mi++) {
        int r0 = bm + wm + mi * 16 + gid;
        #pragma unroll
        for (int ni = 0; ni < 4; ni++) {
            int col = bn + wn + ni * 8 + tig * 2;
            float b0 = bias[col], b1 = bias[col + 1];
            *(__nv_bfloat162*)&Cb[(size_t)r0 * ldc + col] =
                __floats2bfloat162_rn(c[mi][ni][0] + b0, c[mi][ni][1] + b1);
            *(__nv_bfloat162*)&Cb[(size_t)(r0 + 8) * ldc + col] =
                __floats2bfloat162_rn(c[mi][ni][2] + b0, c[mi][ni][3] + b1);
        }
    }
}

// =====================================================================
// 4) gating
// =====================================================================
__global__ void gating_kernel(const float* __restrict__ H, const int* __restrict__ labels,
                              const float* __restrict__ W2, const float* __restrict__ b2,
                              float* __restrict__ w)
{
    int warp = threadIdx.x >> 5, lane = threadIdx.x & 31;
    int b = blockIdx.x * 8 + warp;
    if (b >= BATCH) return;
    int r = labels[b];
    const float* h  = H + (size_t)b * DIM + r * 128;
    const float* w2 = W2 + r * (HIDN * NS);
    float acc[NS] = {0, 0, 0, 0, 0, 0};
    for (int j = lane; j < HIDN; j += 32) {
        float hv = h[j];
        #pragma unroll
        for (int s = 0; s < NS; s++) acc[s] += hv * w2[j * NS + s];
    }
    #pragma unroll
    for (int s = 0; s < NS; s++)
        #pragma unroll
        for (int o = 16; o > 0; o >>= 1)
            acc[s] += __shfl_down_sync(0xffffffffu, acc[s], o);
    if (lane == 0) {
        float m = -1e30f;
        #pragma unroll
        for (int s = 0; s < NS; s++) { acc[s] += b2[r * NS + s]; m = fmaxf(m, acc[s]); }
        float sum = 0.f;
        #pragma unroll
        for (int s = 0; s < NS; s++) { acc[s] = expf(acc[s] - m); sum += acc[s]; }
        float inv = 1.f / sum;
        #pragma unroll
        for (int s = 0; s < NS; s++) w[(size_t)b * NS + s] = acc[s] * inv;
    }
}

// =====================================================================
// 5) scores -> softmax -> combine weights -> scaled coeffs cs
// =====================================================================
__global__ __launch_bounds__(128) void score_kernel(
    const __nv_bfloat16* __restrict__ Qb, const __nv_bfloat16* __restrict__ Kb,
    const float* __restrict__ coeffs, const float* __restrict__ wts,
    float* __restrict__ cs)
{
    int b = blockIdx.x;
    int h = threadIdx.x >> 5, lane = threadIdx.x & 31;
    int t = threadIdx.x;
    __shared__ __nv_bfloat16 sq[NS * DIM];
    __shared__ __nv_bfloat16 sk[NS * DIM];
    __shared__ float sco[DIM];
    __shared__ float wg[NS];
    __shared__ float att[NHEAD][NS][NS];
    __shared__ float ww[NHEAD][NS];

    const uint4* qs = (const uint4*)(Qb + (size_t)b * NS * DIM);
    const uint4* ks = (const uint4*)(Kb + (size_t)b * NS * DIM);
    uint4* qd = (uint4*)sq;
    uint4* kd = (uint4*)sk;
    #pragma unroll
    for (int i = 0; i < 3; i++) {
        qd[t + i * 128] = qs[t + i * 128];
        kd[t + i * 128] = ks[t + i * 128];
    }
    ((float4*)sco)[t] = ((const float4*)(coeffs + (size_t)b * DIM))[t];
    if (t < NS) wg[t] = wts[(size_t)b * NS + t];
    __syncthreads();

    const __nv_bfloat162* q2 = (const __nv_bfloat162*)sq + h * 64;
    const __nv_bfloat162* k2 = (const __nv_bfloat162*)sk + h * 64;
    const float scale = 0.08838834764831845f;
    for (int p = lane; p < NS * NS; p += 32) {
        int i = p / NS, j = p % NS;
        const __nv_bfloat162* qi = q2 + i * 256;
        const __nv_bfloat162* kj = k2 + j * 256;
        float s0 = 0.f;
        #pragma unroll 16
        for (int d = 0; d < 64; d++) {
            float2 qa = __bfloat1622float2(qi[d]);
            float2 kb = __bfloat1622float2(kj[d]);
            s0 += qa.x * kb.x + qa.y * kb.y;
        }
        att[h][i][j] = s0 * scale;
    }
    __syncwarp();
    if (lane < NS) {
        int i = lane;
        float m = -1e30f;
        #pragma unroll
        for (int j = 0; j < NS; j++) m = fmaxf(m, att[h][i][j]);
        float e[NS], sum = 0.f;
        #pragma unroll
        for (int j = 0; j < NS; j++) { e[j] = expf(att[h][i][j] - m); sum += e[j]; }
        float inv = 1.f / sum;
        #pragma unroll
        for (int j = 0; j < NS; j++) att[h][i][j] = e[j] * inv;
    }
    __syncwarp();
    if (lane < NS) {
        int j = lane;
        float s = 0.f;
        #pragma unroll
        for (int i = 0; i < NS; i++) s += wg[i] * att[h][i][j];
        ww[h][j] = s;
    }
    __syncwarp();

    float wl[NS];
    #pragma unroll
    for (int j = 0; j < NS; j++) wl[j] = ww[h][j];

    float* crow = cs + ((size_t)b * NHEAD + h) * KEXT;
    #pragma unroll
    for (int kk = 0; kk < 16; kk++) {
        int k = kk * 32 + lane;
        int sl = (k < 16) ? 0 : (k < 32) ? 1 : (k < 64) ? 2 :
                 (k < 128) ? 3 : (k < 256) ? 4 : 5;
        crow[k] = wl[sl] * sco[k];
    }
    if (lane < 16) crow[512 + lane] = (lane < NS) ? wl[lane] : 0.f;
}

// =====================================================================
// 6) residual + layernorm
// =====================================================================
__global__ __launch_bounds__(256) void ln_kernel(
    const float* __restrict__ x, const float* __restrict__ agg,
    const float* __restrict__ g, const float* __restrict__ be,
    float* __restrict__ out)
{
    int b = blockIdx.x, tid = threadIdx.x;
    __shared__ float rs[8], rq[8];
    size_t base = (size_t)b * DIM;
    float y0 = x[base + tid]       + agg[base + tid];
    float y1 = x[base + tid + 256] + agg[base + tid + 256];
    float s = y0 + y1, q = y0 * y0 + y1 * y1;
    #pragma unroll
    for (int o = 16; o > 0; o >>= 1) {
        s += __shfl_down_sync(0xffffffffu, s, o);
        q += __shfl_down_sync(0xffffffffu, q, o);
    }
    int warp = tid >> 5, lane = tid & 31;
    if (lane == 0) { rs[warp] = s; rq[warp] = q; }
    __syncthreads();
    if (tid == 0) {
        float ts = 0.f, tq = 0.f;
        #pragma unroll
        for (int i = 0; i < 8; i++) { ts += rs[i]; tq += rq[i]; }
        rs[0] = ts; rq[0] = tq;
    }
    __syncthreads();
    float mu  = rs[0] * (1.f / DIM);
    float var = rq[0] * (1.f / DIM) - mu * mu;
    float rstd = rsqrtf(var + 1e-5f);
    out[base + tid]       = (y0 - mu) * rstd * g[tid]       + be[tid];
    out[base + tid + 256] = (y1 - mu) * rstd * g[tid + 256] + be[tid + 256];
}

// =====================================================================
// host
// =====================================================================
extern "C" void kernel_launch(void* const* d_in, const int* in_sizes, int n_in,
                              void* d_out, int out_size)
{
    bool ins = (in_sizes[0] == BATCH * DIM);
    auto P = [&](int i_ins, int i_alpha) -> const float* {
        return (const float*)d_in[ins ? i_ins : i_alpha];
    };
    const float* x   = P(0, 17);
    const float* W1  = P(1, 0);
    const float* b1  = P(2, 7);
    const float* W2  = P(3, 1);
    const float* b2  = P(4, 8);
    const float* Wp  = P(5, 4);
    const float* bp  = P(6, 11);
    const float* Wq  = P(7, 5);  const float* bq = P(8, 12);
    const float* Wk  = P(9, 2);  const float* bk = P(10, 9);
    const float* Wv  = P(11, 6); const float* bv = P(12, 13);
    const float* Wo  = P(13, 3); const float* bo = P(14, 10);
    const float* lng = P(15, 15);
    const float* lnb = P(16, 14);
    const int* labels = (const int*)d_in[ins ? 17 : 16];
    float* out = (float*)d_out;

    float *coeffs, *H, *wts, *W1cat, *biasH, *Apack, *Wf, *Wfv, *biasf, *part, *cs, *pre, *agg;
    __nv_bfloat16 *coeffsb, *WfT, *Qb, *Kb;
    cudaGetSymbolAddress((void**)&coeffs,  g_coeffs);
    cudaGetSymbolAddress((void**)&coeffsb, g_coeffsb);
    cudaGetSymbolAddress((void**)&H,       g_H);
    cudaGetSymbolAddress((void**)&wts,     g_wts);
    cudaGetSymbolAddress((void**)&W1cat,   g_W1cat);
    cudaGetSymbolAddress((void**)&biasH,   g_biasH);
    cudaGetSymbolAddress((void**)&Apack,   g_Apack);
    cudaGetSymbolAddress((void**)&Wf,      g_Wf);
    cudaGetSymbolAddress((void**)&WfT,     g_WfT);
    cudaGetSymbolAddress((void**)&Wfv,     g_Wfv);
    cudaGetSymbolAddress((void**)&biasf,   g_biasf);
    cudaGetSymbolAddress((void**)&part,    g_bias_part);
    cudaGetSymbolAddress((void**)&Qb,      g_Qb);
    cudaGetSymbolAddress((void**)&Kb,      g_Kb);
    cudaGetSymbolAddress((void**)&cs,      g_cs);
    cudaGetSymbolAddress((void**)&pre,     g_pre);
    cudaGetSymbolAddress((void**)&agg,     g_agg);

    // 1. wavelet transform (fp32 + bf16)
    dwt_kernel<<<BATCH, 256>>>(x, coeffs, coeffsb);

    // 2. weight repack + fused-weight GEMMs + transposed bf16 copy + biases
    prep_pack<<<512, 512>>>(W1, b1, Wp, W1cat, biasH, Apack, Wfv);
    gemm_wf<<<dim3(4, 4, 3), 256>>>(Apack, Wq, Wk, Wv, Wf, Wfv);
    transp_bf16<<<dim3(16, 16, 2), dim3(32, 8)>>>(Wf, WfT);
    prep_bias_part<<<dim3(18, 4, 8), 128>>>(bp, Wq, Wk, Wv, part);
    prep_bias_red<<<dim3(18, 4), 128>>>(part, bq, bk, bv, biasf, Wfv);

    // 3. gating
    gemm_tf32<<<dim3(4, 64), 256>>>(x, DIM, W1cat, DIM, H, DIM, DIM, biasH, 1);
    gating_kernel<<<BATCH / 8, 256>>>(H, labels, W2, b2, wts);

    // 4. q,k in bf16 (12 slice-GEMMs, one bf16 tensor-core launch)
    gemm_qk_bf16<<<dim3(4, 64, 12), 256>>>(coeffsb, WfT, biasf, Qb, Kb);

    // 5. scores + softmax + gate combine -> scaled coefficients
    score_kernel<<<BATCH, 128>>>(Qb, Kb, coeffs, wts, cs);

    // 6. pre = cs_h @ Wfv_ext
    gemm_vpre<<<dim3(1, 64, 4), 256>>>(cs, Wfv, pre);

    // 7. output projection + residual + layernorm
    gemm_tf32<<<dim3(4, 64), 256>>>(pre, DIM, Wo, DIM, agg, DIM, DIM, bo, 0);
    ln_kernel<<<BATCH, 256>>>(x, agg, lng, lnb, out);
}

// round 6
// speedup vs baseline: 3.1534x; 1.0745x over previous
#include <cuda_runtime.h>
#include <cuda_bf16.h>
#include <math.h>

#define BATCH 8192
#define DIM   512
#define NREG  4
#define NS    6
#define HIDN  128
#define NHEAD 4
#define HD    128
#define KEXT  528   // 512 coeffs + 6 ww slots + 10 pad

// db8 lowpass (pywt 'periodization')
__constant__ float c_lo[16] = {
    -0.00011747678400228192f, 0.0006754494059985568f, -0.0003917403729959771f,
    -0.00487035299301066f,    0.008746094047015655f,  0.013981027917015516f,
    -0.04408825393106472f,    -0.01736930100202211f,  0.128747426620186f,
    0.00047248457399797254f,  -0.2840155429624281f,   -0.015829105256023893f,
    0.5853546836548691f,      0.6756307362980128f,    0.3128715909144659f,
    0.05441584224308161f
};

__constant__ int c_off[NS] = {0, 16, 32, 64, 128, 256};
__constant__ int c_len[NS] = {16, 16, 32, 64, 128, 256};

// ---- scratch ----
__device__ float g_coeffs[BATCH * DIM];
__device__ __nv_bfloat16 g_coeffsb[BATCH * DIM];
__device__ __nv_bfloat16 g_xb[BATCH * DIM];
__device__ float g_H[BATCH * DIM];
__device__ float g_wts[BATCH * NS];
__device__ float g_W1cat[DIM * DIM];
__device__ float g_biasH[DIM];
__device__ float g_Apack[DIM * DIM];
__device__ float g_Wf[2 * DIM * DIM];                 // fused Wq, Wk (fp32)
__device__ float g_Wfv[KEXT * DIM];                   // fused Wv + bias rows
__device__ float g_biasf[2 * NS * DIM];
__device__ float g_bias_part[8 * 18 * DIM];
__device__ __nv_bfloat16 g_WfT[2 * DIM * DIM];        // [n][k]
__device__ __nv_bfloat16 g_W1catT[DIM * DIM];         // [n][k]
__device__ __nv_bfloat16 g_WfvT[DIM * KEXT];          // [n=512][k=528]
__device__ __nv_bfloat16 g_WoT[DIM * DIM];            // [n][k]
__device__ __nv_bfloat16 g_Qb[BATCH * NS * DIM];
__device__ __nv_bfloat16 g_Kb[BATCH * NS * DIM];
__device__ __nv_bfloat16 g_csb[(size_t)BATCH * NHEAD * KEXT]; // bf16 (34.5 MB)
__device__ __nv_bfloat16 g_preb[BATCH * DIM];
__device__ float g_agg[BATCH * DIM];

// =====================================================================
// 1) DWT (emits fp32 + bf16 coeffs, and bf16 x)
// =====================================================================
__global__ void dwt_kernel(const float* __restrict__ x, float* __restrict__ coeffs,
                           __nv_bfloat16* __restrict__ coeffsb,
                           __nv_bfloat16* __restrict__ xb)
{
    int b = blockIdx.x;
    __shared__ float buf0[DIM], buf1[DIM];
    float* cur = buf0;
    float* nxt = buf1;
    for (int d = threadIdx.x; d < DIM; d += blockDim.x) {
        float v = x[(size_t)b * DIM + d];
        cur[d] = v;
        xb[(size_t)b * DIM + d] = __float2bfloat16(v);
    }
    __syncthreads();

    int n = DIM;
    #pragma unroll
    for (int lev = 0; lev < 5; lev++) {
        int nh = n >> 1;
        for (int k = threadIdx.x; k < nh; k += blockDim.x) {
            float sa = 0.f, sd = 0.f;
            #pragma unroll
            for (int j = 0; j < 16; j++) {
                int m = 2 * k + 1 - j;
                if (m < 0) m += n;
                float av = cur[m];
                float hj = c_lo[15 - j] * ((j & 1) ? 1.f : -1.f);
                sa += c_lo[j] * av;
                sd += hj * av;
            }
            nxt[k] = sa;
            coeffs[(size_t)b * DIM + nh + k]  = sd;
            coeffsb[(size_t)b * DIM + nh + k] = __float2bfloat16(sd);
        }
        __syncthreads();
        float* t = cur; cur = nxt; nxt = t;
        n = nh;
    }
    for (int k = threadIdx.x; k < 16; k += blockDim.x) {
        coeffs[(size_t)b * DIM + k]  = cur[k];
        coeffsb[(size_t)b * DIM + k] = __float2bfloat16(cur[k]);
    }
}

// =====================================================================
// 2) weight repacking
// =====================================================================
__global__ void prep_pack(const float* __restrict__ W1, const float* __restrict__ b1,
                          const float* __restrict__ Wp,
                          float* __restrict__ W1cat, float* __restrict__ biasH,
                          float* __restrict__ Apack, float* __restrict__ Wfv)
{
    int row = blockIdx.x;
    int c   = threadIdx.x;
    int r = c >> 7, j = c & 127;
    W1cat[row * DIM + c] = W1[r * (516 * 128) + row * 128 + j];

    int s, k;
    if      (row < 16)  { s = 0; k = row;       }
    else if (row < 32)  { s = 1; k = row - 16;  }
    else if (row < 64)  { s = 2; k = row - 32;  }
    else if (row < 128) { s = 3; k = row - 64;  }
    else if (row < 256) { s = 4; k = row - 128; }
    else                { s = 5; k = row - 256; }
    Apack[row * DIM + c] = Wp[s * (DIM * DIM) + k * DIM + c];

    if (row == 0)
        biasH[c] = b1[r * 128 + j] + W1[r * (516 * 128) + (512 + r) * 128 + j];
    if (row < KEXT - 518)
        Wfv[(518 + row) * DIM + c] = 0.f;
}

__global__ void prep_bias_part(const float* __restrict__ bp,
                               const float* __restrict__ Wq, const float* __restrict__ Wk,
                               const float* __restrict__ Wv, float* __restrict__ part)
{
    int z = blockIdx.x;
    int t = z / NS, s = z % NS;
    int d = blockIdx.y * 128 + threadIdx.x;
    int e0 = blockIdx.z * 64;
    const float* W = (t == 0) ? Wq : (t == 1) ? Wk : Wv;
    const float* b = bp + s * DIM + e0;
    const float* Wc = W + (size_t)e0 * DIM + d;
    float a = 0.f;
    #pragma unroll
    for (int e = 0; e < 64; e++)
        a += b[e] * Wc[(size_t)e * DIM];
    part[(blockIdx.z * 18 + z) * DIM + d] = a;
}

__global__ void prep_bias_red(const float* __restrict__ part,
                              const float* __restrict__ bq, const float* __restrict__ bk,
                              const float* __restrict__ bv,
                              float* __restrict__ biasf, float* __restrict__ Wfv)
{
    int z = blockIdx.x;
    int t = z / NS, s = z % NS;
    int d = blockIdx.y * 128 + threadIdx.x;
    float a = 0.f;
    #pragma unroll
    for (int i = 0; i < 8; i++)
        a += part[(i * 18 + z) * DIM + d];
    const float* bvec = (t == 0) ? bq : (t == 1) ? bk : bv;
    a += bvec[d];
    if (t < 2) biasf[(t * NS + s) * DIM + d] = a;
    else       Wfv[(512 + s) * DIM + d] = a;
}

// guarded tiled transpose + bf16 convert for 5 operand jobs.
// src [K][N=512] -> dst [N=512][K]  (dst row stride = K)
__global__ void transp_jobs(const float* __restrict__ Wf, const float* __restrict__ W1cat,
                            const float* __restrict__ Wfv, const float* __restrict__ Wo,
                            __nv_bfloat16* __restrict__ WfT,
                            __nv_bfloat16* __restrict__ W1catT,
                            __nv_bfloat16* __restrict__ WfvT,
                            __nv_bfloat16* __restrict__ WoT)
{
    int job = blockIdx.z;
    const float* src;
    __nv_bfloat16* dst;
    int K;
    switch (job) {
        case 0: src = Wf;                 dst = WfT;                 K = DIM;  break;
        case 1: src = Wf + DIM * DIM;     dst = WfT + DIM * DIM;     K = DIM;  break;
        case 2: src = W1cat;              dst = W1catT;              K = DIM;  break;
        case 3: src = Wfv;                dst = WfvT;                K = KEXT; break;
        default: src = Wo;                dst = WoT;                 K = DIM;  break;
    }
    __shared__ float tile[32][33];
    int k0 = blockIdx.y * 32, n0 = blockIdx.x * 32;
    if (k0 >= K) return;
    for (int i = threadIdx.y; i < 32; i += 8)
        if (k0 + i < K)
            tile[i][threadIdx.x] = src[(size_t)(k0 + i) * DIM + n0 + threadIdx.x];
    __syncthreads();
    for (int i = threadIdx.y; i < 32; i += 8)
        if (k0 + threadIdx.x < K)
            dst[(size_t)(n0 + i) * K + k0 + threadIdx.x] =
                __float2bfloat16(tile[threadIdx.x][i]);
}

// =====================================================================
// 3) tf32 tensor-core GEMM (only for the small Wf prep)
// =====================================================================
__device__ __forceinline__ void cp16(void* dst, const void* src) {
    unsigned d = (unsigned)__cvta_generic_to_shared(dst);
    asm volatile("cp.async.ca.shared.global [%0], [%1], 16;" :: "r"(d), "l"(src));
}

__device__ __forceinline__ void gemm_tile(
    const float* __restrict__ A, int lda,
    const float* __restrict__ B, int ldb,
    float* __restrict__ C, int ldc, int K,
    int bm, int bn)
{
    __shared__ float As[2][128][20];
    __shared__ float Bs[2][16][136];
    int t = threadIdx.x;
    int warp = t >> 5, lane = t & 31;
    int wm = (warp >> 2) * 64;
    int wn = (warp & 3) * 32;
    int gid = lane >> 2, tig = lane & 3;

    int aRow = t >> 2, aC = (t & 3) << 2;
    int bRow = t >> 5, bC = (t & 31) << 2;
    const float* Ab = A + (size_t)bm * lda;
    int nk = K >> 4;

    cp16(&As[0][aRow][aC],      &Ab[(size_t)aRow * lda + aC]);
    cp16(&As[0][aRow + 64][aC], &Ab[(size_t)(aRow + 64) * lda + aC]);
    cp16(&Bs[0][bRow][bC],      &B[(size_t)bRow * ldb + bn + bC]);
    cp16(&Bs[0][bRow + 8][bC],  &B[(size_t)(bRow + 8) * ldb + bn + bC]);
    asm volatile("cp.async.commit_group;");

    float c[4][4][4] = {};

    for (int i = 0; i < nk; i++) {
        if (i + 1 < nk) {
            int st = (i + 1) & 1, k0 = (i + 1) << 4;
            cp16(&As[st][aRow][aC],      &Ab[(size_t)aRow * lda + k0 + aC]);
            cp16(&As[st][aRow + 64][aC], &Ab[(size_t)(aRow + 64) * lda + k0 + aC]);
            cp16(&Bs[st][bRow][bC],      &B[(size_t)(k0 + bRow) * ldb + bn + bC]);
            cp16(&Bs[st][bRow + 8][bC],  &B[(size_t)(k0 + bRow + 8) * ldb + bn + bC]);
            asm volatile("cp.async.commit_group;");
            asm volatile("cp.async.wait_group 1;");
        } else {
            asm volatile("cp.async.wait_group 0;");
        }
        __syncthreads();
        int st = i & 1;
        #pragma unroll
        for (int kk = 0; kk < 16; kk += 8) {
            unsigned a[4][4], b[4][2];
            #pragma unroll
            for (int mi = 0; mi < 4; mi++) {
                const float* p = &As[st][wm + mi * 16 + gid][kk + tig];
                a[mi][0] = __float_as_uint(p[0]);
                a[mi][1] = __float_as_uint(p[8 * 20]);
                a[mi][2] = __float_as_uint(p[4]);
                a[mi][3] = __float_as_uint(p[8 * 20 + 4]);
            }
            #pragma unroll
            for (int ni = 0; ni < 4; ni++) {
                const float* p = &Bs[st][kk + tig][wn + ni * 8 + gid];
                b[ni][0] = __float_as_uint(p[0]);
                b[ni][1] = __float_as_uint(p[4 * 136]);
            }
            #pragma unroll
            for (int mi = 0; mi < 4; mi++)
                #pragma unroll
                for (int ni = 0; ni < 4; ni++)
                    asm volatile(
                        "mma.sync.aligned.m16n8k8.row.col.f32.tf32.tf32.f32 "
                        "{%0,%1,%2,%3}, {%4,%5,%6,%7}, {%8,%9}, {%0,%1,%2,%3};"
                        : "+f"(c[mi][ni][0]), "+f"(c[mi][ni][1]),
                          "+f"(c[mi][ni][2]), "+f"(c[mi][ni][3])
                        : "r"(a[mi][0]), "r"(a[mi][1]), "r"(a[mi][2]), "r"(a[mi][3]),
                          "r"(b[ni][0]), "r"(b[ni][1]));
        }
        __syncthreads();
    }

    #pragma unroll
    for (int mi = 0; mi < 4; mi++) {
        int r0 = bm + wm + mi * 16 + gid;
        #pragma unroll
        for (int ni = 0; ni < 4; ni++) {
            int col = bn + wn + ni * 8 + tig * 2;
            *(float2*)&C[(size_t)r0 * ldc + col] =
                make_float2(c[mi][ni][0], c[mi][ni][1]);
            *(float2*)&C[(size_t)(r0 + 8) * ldc + col] =
                make_float2(c[mi][ni][2], c[mi][ni][3]);
        }
    }
}

__global__ __launch_bounds__(256, 2) void gemm_wf(
    const float* __restrict__ Apack,
    const float* __restrict__ Wq, const float* __restrict__ Wk,
    const float* __restrict__ Wv, float* __restrict__ Wf, float* __restrict__ Wfv)
{
    int z = blockIdx.z;
    const float* B = (z == 0) ? Wq : (z == 1) ? Wk : Wv;
    float* C = (z == 2) ? Wfv : Wf + (size_t)z * DIM * DIM;
    gemm_tile(Apack, DIM, B, DIM, C, DIM, DIM,
              blockIdx.y * 128, blockIdx.x * 128);
}

// =====================================================================
// 3b) generic bf16 tensor-core GEMM tile: mma.m16n8k16, BK=16
//     A [m][k] row-major (lda), B [n][k] (ldb). fp32 or bf16 out.
// =====================================================================
__device__ __forceinline__ void gemm_bf16_tile(
    const __nv_bfloat16* __restrict__ A, int lda,
    const __nv_bfloat16* __restrict__ B, int ldb,
    float* __restrict__ Cf, __nv_bfloat16* __restrict__ Cb, int ldc, int K,
    const float* __restrict__ bias, int doRelu,
    int bm, int bn)
{
    __shared__ __nv_bfloat16 As[2][128 * 24];
    __shared__ __nv_bfloat16 Bs[2][128 * 24];
    int tid = threadIdx.x, warp = tid >> 5, lane = tid & 31;
    int wm = (warp >> 2) * 64, wn = (warp & 3) * 32;
    int gid = lane >> 2, tig = lane & 3;
    int lRow = tid >> 1, lSeg = (tid & 1) * 8;

    const __nv_bfloat16* Ab = A + (size_t)bm * lda;
    const __nv_bfloat16* Bb = B + (size_t)bn * ldb;
    int nk = K >> 4;

    cp16(&As[0][lRow * 24 + lSeg], &Ab[(size_t)lRow * lda + lSeg]);
    cp16(&Bs[0][lRow * 24 + lSeg], &Bb[(size_t)lRow * ldb + lSeg]);
    asm volatile("cp.async.commit_group;");

    float c[4][4][4] = {};

    for (int i = 0; i < nk; i++) {
        if (i + 1 < nk) {
            int st = (i + 1) & 1, k0 = (i + 1) << 4;
            cp16(&As[st][lRow * 24 + lSeg], &Ab[(size_t)lRow * lda + k0 + lSeg]);
            cp16(&Bs[st][lRow * 24 + lSeg], &Bb[(size_t)lRow * ldb + k0 + lSeg]);
            asm volatile("cp.async.commit_group;");
            asm volatile("cp.async.wait_group 1;");
        } else {
            asm volatile("cp.async.wait_group 0;");
        }
        __syncthreads();
        int st = i & 1;
        unsigned a[4][4], bfr[4][2];
        #pragma unroll
        for (int mi = 0; mi < 4; mi++) {
            const __nv_bfloat16* p = &As[st][(wm + mi * 16 + gid) * 24 + 2 * tig];
            a[mi][0] = *(const unsigned*)p;
            a[mi][1] = *(const unsigned*)(p + 8 * 24);
            a[mi][2] = *(const unsigned*)(p + 8);
            a[mi][3] = *(const unsigned*)(p + 8 * 24 + 8);
        }
        #pragma unroll
        for (int ni = 0; ni < 4; ni++) {
            const __nv_bfloat16* p = &Bs[st][(wn + ni * 8 + gid) * 24 + 2 * tig];
            bfr[ni][0] = *(const unsigned*)p;
            bfr[ni][1] = *(const unsigned*)(p + 8);
        }
        #pragma unroll
        for (int mi = 0; mi < 4; mi++)
            #pragma unroll
            for (int ni = 0; ni < 4; ni++)
                asm volatile(
                    "mma.sync.aligned.m16n8k16.row.col.f32.bf16.bf16.f32 "
                    "{%0,%1,%2,%3}, {%4,%5,%6,%7}, {%8,%9}, {%0,%1,%2,%3};"
                    : "+f"(c[mi][ni][0]), "+f"(c[mi][ni][1]),
                      "+f"(c[mi][ni][2]), "+f"(c[mi][ni][3])
                    : "r"(a[mi][0]), "r"(a[mi][1]), "r"(a[mi][2]), "r"(a[mi][3]),
                      "r"(bfr[ni][0]), "r"(bfr[ni][1]));
        __syncthreads();
    }

    #pragma unroll
    for (int mi = 0; mi < 4; mi++) {
        int r0 = bm + wm + mi * 16 + gid;
        #pragma unroll
        for (int ni = 0; ni < 4; ni++) {
            int col = bn + wn + ni * 8 + tig * 2;
            float b0 = 0.f, b1 = 0.f;
            if (bias) { b0 = bias[col]; b1 = bias[col + 1]; }
            float v0 = c[mi][ni][0] + b0, v1 = c[mi][ni][1] + b1;
            float v2 = c[mi][ni][2] + b0, v3 = c[mi][ni][3] + b1;
            if (doRelu) {
                v0 = fmaxf(v0, 0.f); v1 = fmaxf(v1, 0.f);
                v2 = fmaxf(v2, 0.f); v3 = fmaxf(v3, 0.f);
            }
            if (Cb) {
                *(__nv_bfloat162*)&Cb[(size_t)r0 * ldc + col] =
                    __floats2bfloat162_rn(v0, v1);
                *(__nv_bfloat162*)&Cb[(size_t)(r0 + 8) * ldc + col] =
                    __floats2bfloat162_rn(v2, v3);
            } else {
                *(float2*)&Cf[(size_t)r0 * ldc + col]       = make_float2(v0, v1);
                *(float2*)&Cf[(size_t)(r0 + 8) * ldc + col] = make_float2(v2, v3);
            }
        }
    }
}

// generic fp32-out bf16 GEMM (H and Wo)
__global__ __launch_bounds__(256, 2) void gemm_bf16(
    const __nv_bfloat16* __restrict__ A, int lda,
    const __nv_bfloat16* __restrict__ B, int ldb,
    float* __restrict__ C, int ldc, int K,
    const float* __restrict__ bias, int doRelu)
{
    gemm_bf16_tile(A, lda, B, ldb, C, nullptr, ldc, K, bias, doRelu,
                   blockIdx.y * 128, blockIdx.x * 128);
}

// q,k slices: z in 0..11 -> (t, s)
__global__ __launch_bounds__(256, 2) void gemm_qk_bf16(
    const __nv_bfloat16* __restrict__ coeffsb, const __nv_bfloat16* __restrict__ WfT,
    const float* __restrict__ biasf,
    __nv_bfloat16* __restrict__ Qb, __nv_bfloat16* __restrict__ Kb)
{
    int z = blockIdx.z;
    int t = z / NS, s = z % NS;
    int off = c_off[s], len = c_len[s];
    __nv_bfloat16* Cb = (t == 0 ? Qb : Kb) + s * DIM;
    gemm_bf16_tile(coeffsb + off, DIM,
                   WfT + (size_t)t * DIM * DIM + off, DIM,
                   nullptr, Cb, NS * DIM, len,
                   biasf + (t * NS + s) * DIM, 0,
                   blockIdx.y * 128, blockIdx.x * 128);
}

// pre[:, h*128:(h+1)*128] = cs_h @ WfvT rows h*128.., K=528
__global__ __launch_bounds__(256, 2) void gemm_vpre_bf16(
    const __nv_bfloat16* __restrict__ csb, const __nv_bfloat16* __restrict__ WfvT,
    __nv_bfloat16* __restrict__ preb)
{
    int h = blockIdx.z;
    gemm_bf16_tile(csb + (size_t)h * KEXT, NHEAD * KEXT,
                   WfvT + (size_t)h * HD * KEXT, KEXT,
                   nullptr, preb + h * HD, DIM, KEXT,
                   nullptr, 0,
                   blockIdx.y * 128, 0);
}

// =====================================================================
// 4) gating
// =====================================================================
__global__ void gating_kernel(const float* __restrict__ H, const int* __restrict__ labels,
                              const float* __restrict__ W2, const float* __restrict__ b2,
                              float* __restrict__ w)
{
    int warp = threadIdx.x >> 5, lane = threadIdx.x & 31;
    int b = blockIdx.x * 8 + warp;
    if (b >= BATCH) return;
    int r = labels[b];
    const float* h  = H + (size_t)b * DIM + r * 128;
    const float* w2 = W2 + r * (HIDN * NS);
    float acc[NS] = {0, 0, 0, 0, 0, 0};
    for (int j = lane; j < HIDN; j += 32) {
        float hv = h[j];
        #pragma unroll
        for (int s = 0; s < NS; s++) acc[s] += hv * w2[j * NS + s];
    }
    #pragma unroll
    for (int s = 0; s < NS; s++)
        #pragma unroll
        for (int o = 16; o > 0; o >>= 1)
            acc[s] += __shfl_down_sync(0xffffffffu, acc[s], o);
    if (lane == 0) {
        float m = -1e30f;
        #pragma unroll
        for (int s = 0; s < NS; s++) { acc[s] += b2[r * NS + s]; m = fmaxf(m, acc[s]); }
        float sum = 0.f;
        #pragma unroll
        for (int s = 0; s < NS; s++) { acc[s] = expf(acc[s] - m); sum += acc[s]; }
        float inv = 1.f / sum;
        #pragma unroll
        for (int s = 0; s < NS; s++) w[(size_t)b * NS + s] = acc[s] * inv;
    }
}

// =====================================================================
// 5) scores -> softmax -> combine weights -> scaled coeffs (bf16)
// =====================================================================
__global__ __launch_bounds__(128) void score_kernel(
    const __nv_bfloat16* __restrict__ Qb, const __nv_bfloat16* __restrict__ Kb,
    const float* __restrict__ coeffs, const float* __restrict__ wts,
    __nv_bfloat16* __restrict__ csb)
{
    int b = blockIdx.x;
    int h = threadIdx.x >> 5, lane = threadIdx.x & 31;
    int t = threadIdx.x;
    __shared__ __nv_bfloat16 sq[NS * DIM];
    __shared__ __nv_bfloat16 sk[NS * DIM];
    __shared__ float sco[DIM];
    __shared__ float wg[NS];
    __shared__ float att[NHEAD][NS][NS];
    __shared__ float ww[NHEAD][NS];

    const uint4* qs = (const uint4*)(Qb + (size_t)b * NS * DIM);
    const uint4* ks = (const uint4*)(Kb + (size_t)b * NS * DIM);
    uint4* qd = (uint4*)sq;
    uint4* kd = (uint4*)sk;
    #pragma unroll
    for (int i = 0; i < 3; i++) {
        qd[t + i * 128] = qs[t + i * 128];
        kd[t + i * 128] = ks[t + i * 128];
    }
    ((float4*)sco)[t] = ((const float4*)(coeffs + (size_t)b * DIM))[t];
    if (t < NS) wg[t] = wts[(size_t)b * NS + t];
    __syncthreads();

    const __nv_bfloat162* q2 = (const __nv_bfloat162*)sq + h * 64;
    const __nv_bfloat162* k2 = (const __nv_bfloat162*)sk + h * 64;
    const float scale = 0.08838834764831845f;
    for (int p = lane; p < NS * NS; p += 32) {
        int i = p / NS, j = p % NS;
        const __nv_bfloat162* qi = q2 + i * 256;
        const __nv_bfloat162* kj = k2 + j * 256;
        float s0 = 0.f;
        #pragma unroll 16
        for (int d = 0; d < 64; d++) {
            float2 qa = __bfloat1622float2(qi[d]);
            float2 kb = __bfloat1622float2(kj[d]);
            s0 += qa.x * kb.x + qa.y * kb.y;
        }
        att[h][i][j] = s0 * scale;
    }
    __syncwarp();
    if (lane < NS) {
        int i = lane;
        float m = -1e30f;
        #pragma unroll
        for (int j = 0; j < NS; j++) m = fmaxf(m, att[h][i][j]);
        float e[NS], sum = 0.f;
        #pragma unroll
        for (int j = 0; j < NS; j++) { e[j] = expf(att[h][i][j] - m); sum += e[j]; }
        float inv = 1.f / sum;
        #pragma unroll
        for (int j = 0; j < NS; j++) att[h][i][j] = e[j] * inv;
    }
    __syncwarp();
    if (lane < NS) {
        int j = lane;
        float s = 0.f;
        #pragma unroll
        for (int i = 0; i < NS; i++) s += wg[i] * att[h][i][j];
        ww[h][j] = s;
    }
    __syncwarp();

    float wl[NS];
    #pragma unroll
    for (int j = 0; j < NS; j++) wl[j] = ww[h][j];

    __nv_bfloat16* crow = csb + ((size_t)b * NHEAD + h) * KEXT;
    #pragma unroll
    for (int kk = 0; kk < 16; kk++) {
        int k = kk * 32 + lane;
        int sl = (k < 16) ? 0 : (k < 32) ? 1 : (k < 64) ? 2 :
                 (k < 128) ? 3 : (k < 256) ? 4 : 5;
        crow[k] = __float2bfloat16(wl[sl] * sco[k]);
    }
    if (lane < 16)
        crow[512 + lane] = __float2bfloat16((lane < NS) ? wl[lane] : 0.f);
}

// =====================================================================
// 6) residual + layernorm
// =====================================================================
__global__ __launch_bounds__(256) void ln_kernel(
    const float* __restrict__ x, const float* __restrict__ agg,
    const float* __restrict__ g, const float* __restrict__ be,
    float* __restrict__ out)
{
    int b = blockIdx.x, tid = threadIdx.x;
    __shared__ float rs[8], rq[8];
    size_t base = (size_t)b * DIM;
    float y0 = x[base + tid]       + agg[base + tid];
    float y1 = x[base + tid + 256] + agg[base + tid + 256];
    float s = y0 + y1, q = y0 * y0 + y1 * y1;
    #pragma unroll
    for (int o = 16; o > 0; o >>= 1) {
        s += __shfl_down_sync(0xffffffffu, s, o);
        q += __shfl_down_sync(0xffffffffu, q, o);
    }
    int warp = tid >> 5, lane = tid & 31;
    if (lane == 0) { rs[warp] = s; rq[warp] = q; }
    __syncthreads();
    if (tid == 0) {
        float ts = 0.f, tq = 0.f;
        #pragma unroll
        for (int i = 0; i < 8; i++) { ts += rs[i]; tq += rq[i]; }
        rs[0] = ts; rq[0] = tq;
    }
    __syncthreads();
    float mu  = rs[0] * (1.f / DIM);
    float var = rq[0] * (1.f / DIM) - mu * mu;
    float rstd = rsqrtf(var + 1e-5f);
    out[base + tid]       = (y0 - mu) * rstd * g[tid]       + be[tid];
    out[base + tid + 256] = (y1 - mu) * rstd * g[tid + 256] + be[tid + 256];
}

// =====================================================================
// host
// =====================================================================
extern "C" void kernel_launch(void* const* d_in, const int* in_sizes, int n_in,
                              void* d_out, int out_size)
{
    bool ins = (in_sizes[0] == BATCH * DIM);
    auto P = [&](int i_ins, int i_alpha) -> const float* {
        return (const float*)d_in[ins ? i_ins : i_alpha];
    };
    const float* x   = P(0, 17);
    const float* W1  = P(1, 0);
    const float* b1  = P(2, 7);
    const float* W2  = P(3, 1);
    const float* b2  = P(4, 8);
    const float* Wp  = P(5, 4);
    const float* bp  = P(6, 11);
    const float* Wq  = P(7, 5);  const float* bq = P(8, 12);
    const float* Wk  = P(9, 2);  const float* bk = P(10, 9);
    const float* Wv  = P(11, 6); const float* bv = P(12, 13);
    const float* Wo  = P(13, 3); const float* bo = P(14, 10);
    const float* lng = P(15, 15);
    const float* lnb = P(16, 14);
    const int* labels = (const int*)d_in[ins ? 17 : 16];
    float* out = (float*)d_out;

    float *coeffs, *H, *wts, *W1cat, *biasH, *Apack, *Wf, *Wfv, *biasf, *part, *agg;
    __nv_bfloat16 *coeffsb, *xb, *WfT, *W1catT, *WfvT, *WoT, *Qb, *Kb, *csb, *preb;
    cudaGetSymbolAddress((void**)&coeffs,  g_coeffs);
    cudaGetSymbolAddress((void**)&coeffsb, g_coeffsb);
    cudaGetSymbolAddress((void**)&xb,      g_xb);
    cudaGetSymbolAddress((void**)&H,       g_H);
    cudaGetSymbolAddress((void**)&wts,     g_wts);
    cudaGetSymbolAddress((void**)&W1cat,   g_W1cat);
    cudaGetSymbolAddress((void**)&biasH,   g_biasH);
    cudaGetSymbolAddress((void**)&Apack,   g_Apack);
    cudaGetSymbolAddress((void**)&Wf,      g_Wf);
    cudaGetSymbolAddress((void**)&Wfv,     g_Wfv);
    cudaGetSymbolAddress((void**)&biasf,   g_biasf);
    cudaGetSymbolAddress((void**)&part,    g_bias_part);
    cudaGetSymbolAddress((void**)&WfT,     g_WfT);
    cudaGetSymbolAddress((void**)&W1catT,  g_W1catT);
    cudaGetSymbolAddress((void**)&WfvT,    g_WfvT);
    cudaGetSymbolAddress((void**)&WoT,     g_WoT);
    cudaGetSymbolAddress((void**)&Qb,      g_Qb);
    cudaGetSymbolAddress((void**)&Kb,      g_Kb);
    cudaGetSymbolAddress((void**)&csb,     g_csb);
    cudaGetSymbolAddress((void**)&preb,    g_preb);
    cudaGetSymbolAddress((void**)&agg,     g_agg);

    // 1. wavelet transform (+ bf16 copies of coeffs and x)
    dwt_kernel<<<BATCH, 256>>>(x, coeffs, coeffsb, xb);

    // 2. weight repack + fused-weight GEMMs + biases + bf16 transposes
    prep_pack<<<512, 512>>>(W1, b1, Wp, W1cat, biasH, Apack, Wfv);
    gemm_wf<<<dim3(4, 4, 3), 256>>>(Apack, Wq, Wk, Wv, Wf, Wfv);
    prep_bias_part<<<dim3(18, 4, 8), 128>>>(bp, Wq, Wk, Wv, part);
    prep_bias_red<<<dim3(18, 4), 128>>>(part, bq, bk, bv, biasf, Wfv);
    transp_jobs<<<dim3(16, 17, 5), dim3(32, 8)>>>(Wf, W1cat, Wfv, Wo,
                                                  WfT, W1catT, WfvT, WoT);

    // 3. gating: H = relu(xb @ W1catT + biasH) -> regime select + softmax
    gemm_bf16<<<dim3(4, 64), 256>>>(xb, DIM, W1catT, DIM, H, DIM, DIM, biasH, 1);
    gating_kernel<<<BATCH / 8, 256>>>(H, labels, W2, b2, wts);

    // 4. q,k in bf16
    gemm_qk_bf16<<<dim3(4, 64, 12), 256>>>(coeffsb, WfT, biasf, Qb, Kb);

    // 5. scores + softmax + gate combine -> scaled coefficients (bf16)
    score_kernel<<<BATCH, 128>>>(Qb, Kb, coeffs, wts, csb);

    // 6. pre = cs_h @ Wfv_ext (bf16, K=528)
    gemm_vpre_bf16<<<dim3(1, 64, 4), 256>>>(csb, WfvT, preb);

    // 7. output projection + residual + layernorm
    gemm_bf16<<<dim3(4, 64), 256>>>(preb, DIM, WoT, DIM, agg, DIM, DIM, bo, 0);
    ln_kernel<<<BATCH, 256>>>(x, agg, lng, lnb, out);
}